// round 1
// baseline (speedup 1.0000x reference)
#include <cuda_runtime.h>
#include <math.h>

// ---------------------------------------------------------------------------
// CapsNet forward:
//   conv1 9x9 VALID + bias + relu      -> h1 [256,256,20,20]
//   conv2 9x9 stride2 + bias           -> u_raw [256, 9216]   (b, oc*36+s)
//   primary squash (+ transpose)       -> uT [9216, 256]      (nj, b)
//   dynamic routing (3 iters), WITHOUT materializing u_hat:
//     s[c,i,b]      = sum_{n,j} probs[c,n,i]*W[c,n,i,j]*uT[n*8+j, b]
//     v             = squash_over_batch(s)
//     delta_b[c,n,i]= sum_b (sum_j W[c,n,i,j]*uT[n*8+j,b]) * v[c,i,b]
//   out[b,c] = sum_i v[c,i,b]^2
// ---------------------------------------------------------------------------

// Scratch (device globals; no allocations allowed)
__device__ float g_h1[256 * 256 * 400];        // 105 MB conv1 output
__device__ float g_uraw[256 * 9216];           // conv2 output (pre-squash)
__device__ float g_uT[9216 * 256];             // squashed primary caps, transposed
__device__ float g_blog[10 * 1152 * 16];       // routing logits b
__device__ float g_probs[10 * 1152 * 16];      // softmax(b) over n
__device__ float g_spart[10 * 16 * 16 * 256];  // partial s: [c][chunk][i][b]
__device__ float g_v[10 * 16 * 256];           // routed outputs v[c][i][b]

// ---------------------------------------------------------------------------
// conv1: grid (256 batches, 16 oc-groups of 16), 128 threads.
// Each thread: 4 positions x 16 ocs register tile; x image + w tile in smem.
// ---------------------------------------------------------------------------
__global__ __launch_bounds__(128) void conv1_kernel(const float* __restrict__ x,
                                                    const float* __restrict__ w,
                                                    const float* __restrict__ bias) {
    int b = blockIdx.x, ocg = blockIdx.y;
    __shared__ float xs[784];      // 28x28 image
    __shared__ float ws[16 * 81];  // 16 oc x 81 taps
    int tid = threadIdx.x;
    for (int i = tid; i < 784; i += 128) xs[i] = x[b * 784 + i];
    for (int i = tid; i < 1296; i += 128) ws[i] = w[ocg * 1296 + i];
    __syncthreads();

    int pr[4], pc[4];
    bool val[4];
#pragma unroll
    for (int q = 0; q < 4; q++) {
        int p = tid + q * 128;
        val[q] = (p < 400);
        int pp = val[q] ? p : 0;
        pr[q] = pp / 20;
        pc[q] = pp % 20;
    }
    float acc[4][16];
#pragma unroll
    for (int q = 0; q < 4; q++)
#pragma unroll
        for (int o = 0; o < 16; o++) acc[q][o] = 0.f;

#pragma unroll 1
    for (int kh = 0; kh < 9; kh++) {
        int rb[4];
#pragma unroll
        for (int q = 0; q < 4; q++) rb[q] = (pr[q] + kh) * 28 + pc[q];
#pragma unroll 1
        for (int kw = 0; kw < 9; kw++) {
            float xv[4];
#pragma unroll
            for (int q = 0; q < 4; q++) xv[q] = xs[rb[q] + kw];
            int ko = kh * 9 + kw;
#pragma unroll
            for (int o = 0; o < 16; o++) {
                float wv = ws[o * 81 + ko];
#pragma unroll
                for (int q = 0; q < 4; q++) acc[q][o] = fmaf(xv[q], wv, acc[q][o]);
            }
        }
    }
#pragma unroll
    for (int o = 0; o < 16; o++) {
        float bv = bias[ocg * 16 + o];
#pragma unroll
        for (int q = 0; q < 4; q++) {
            if (val[q]) {
                float v = acc[q][o] + bv;
                g_h1[(b * 256 + ocg * 16 + o) * 400 + tid + q * 128] = fmaxf(v, 0.f);
            }
        }
    }
}

// ---------------------------------------------------------------------------
// conv2 as implicit GEMM: M=256 (oc), N=9216 (b*36+s), K=20736 (ic*81).
// BM=BN=128, BK=32, 256 threads, 8x8 per-thread microtile.
// B tile gathered from g_h1 via per-n base address (smem) + per-k offset.
// Epilogue adds bias and writes directly in u_raw layout.
// ---------------------------------------------------------------------------
__global__ __launch_bounds__(256) void conv2_kernel(const float* __restrict__ w2,
                                                    const float* __restrict__ b2) {
    __shared__ float As[32][128];  // [k][m]
    __shared__ float Bs[32][128];  // [k][n]
    __shared__ int nAddr[128];
    int t = threadIdx.x;
    int m0 = blockIdx.x * 128;
    int n0 = blockIdx.y * 128;

    if (t < 128) {
        int n = n0 + t;
        int bb = n / 36, s = n - bb * 36;
        nAddr[t] = bb * 102400 + (s / 6) * 40 + (s % 6) * 2;
    }
    float acc[8][8];
#pragma unroll
    for (int i = 0; i < 8; i++)
#pragma unroll
        for (int j = 0; j < 8; j++) acc[i][j] = 0.f;

    int tm = (t >> 4) << 3;
    int tn = (t & 15) << 3;
    int kin = t >> 3;        // 0..31
    int nb = (t & 7) << 4;   // 0,16,...,112
    __syncthreads();

    for (int kt = 0; kt < 20736; kt += 32) {
        // fetch A (weights) into regs
        float4 av[4];
#pragma unroll
        for (int q = 0; q < 4; q++) {
            int fid = t * 4 + q;
            int m = fid >> 3;
            int k4 = (fid & 7) << 2;
            av[q] = *(const float4*)&w2[(m0 + m) * 20736 + kt + k4];
        }
        // fetch B (im2col gather) into regs
        int kg = kt + kin;
        int ic = kg / 81;
        int rr = kg - ic * 81;
        int koff = ic * 400 + (rr / 9) * 20 + (rr % 9);
        float bv[16];
#pragma unroll
        for (int q = 0; q < 16; q++) bv[q] = g_h1[nAddr[nb + q] + koff];

        __syncthreads();  // previous compute done
#pragma unroll
        for (int q = 0; q < 4; q++) {
            int fid = t * 4 + q;
            int m = fid >> 3;
            int k4 = (fid & 7) << 2;
            As[k4 + 0][m] = av[q].x;
            As[k4 + 1][m] = av[q].y;
            As[k4 + 2][m] = av[q].z;
            As[k4 + 3][m] = av[q].w;
        }
#pragma unroll
        for (int q = 0; q < 16; q++) Bs[kin][nb + q] = bv[q];
        __syncthreads();

#pragma unroll 8
        for (int kk = 0; kk < 32; kk++) {
            float a[8], bb[8];
            *(float4*)&a[0] = *(float4*)&As[kk][tm];
            *(float4*)&a[4] = *(float4*)&As[kk][tm + 4];
            *(float4*)&bb[0] = *(float4*)&Bs[kk][tn];
            *(float4*)&bb[4] = *(float4*)&Bs[kk][tn + 4];
#pragma unroll
            for (int i = 0; i < 8; i++)
#pragma unroll
                for (int j = 0; j < 8; j++) acc[i][j] = fmaf(a[i], bb[j], acc[i][j]);
        }
    }

#pragma unroll
    for (int j = 0; j < 8; j++) {
        int n = n0 + tn + j;
        int bb = n / 36, s = n - bb * 36;
        int obase = bb * 9216 + s;
#pragma unroll
        for (int i = 0; i < 8; i++) {
            int oc = m0 + tm + i;
            g_uraw[obase + oc * 36] = acc[i][j] + b2[oc];
        }
    }
}

// ---------------------------------------------------------------------------
// primary squash (scale = sq/(1+sq), NO /norm) + transpose to uT[nj][b]
// ---------------------------------------------------------------------------
__global__ __launch_bounds__(256) void squashT_kernel() {
    int idx = blockIdx.x * 256 + threadIdx.x;  // grid 1152 -> 294912
    int n = idx >> 8, b = idx & 255;
    const float4* src = (const float4*)&g_uraw[b * 9216 + n * 8];
    float4 u0 = src[0], u1 = src[1];
    float sq = u0.x * u0.x + u0.y * u0.y + u0.z * u0.z + u0.w * u0.w +
               u1.x * u1.x + u1.y * u1.y + u1.z * u1.z + u1.w * u1.w;
    float sc = sq / (1.0f + sq);
    float r[8] = {u0.x * sc, u0.y * sc, u0.z * sc, u0.w * sc,
                  u1.x * sc, u1.y * sc, u1.z * sc, u1.w * sc};
#pragma unroll
    for (int j = 0; j < 8; j++) g_uT[(n * 8 + j) * 256 + b] = r[j];
}

__global__ void zero_blog_kernel() {
    int i = blockIdx.x * 256 + threadIdx.x;
    if (i < 184320) g_blog[i] = 0.f;
}

// ---------------------------------------------------------------------------
// softmax over n (1152) for each of the 160 (c,i) columns
// ---------------------------------------------------------------------------
__global__ __launch_bounds__(128) void softmax_kernel() {
    int c = blockIdx.x >> 4, i = blockIdx.x & 15;
    int tid = threadIdx.x;
    __shared__ float red[128];
    float vals[9];
    float m = -1e30f;
#pragma unroll
    for (int q = 0; q < 9; q++) {
        int n = tid + q * 128;
        vals[q] = g_blog[(c * 1152 + n) * 16 + i];
        m = fmaxf(m, vals[q]);
    }
    red[tid] = m;
    __syncthreads();
    for (int s2 = 64; s2 > 0; s2 >>= 1) {
        if (tid < s2) red[tid] = fmaxf(red[tid], red[tid + s2]);
        __syncthreads();
    }
    float M = red[0];
    __syncthreads();
    float e[9];
    float sum = 0.f;
#pragma unroll
    for (int q = 0; q < 9; q++) {
        e[q] = expf(vals[q] - M);
        sum += e[q];
    }
    red[tid] = sum;
    __syncthreads();
    for (int s2 = 64; s2 > 0; s2 >>= 1) {
        if (tid < s2) red[tid] += red[tid + s2];
        __syncthreads();
    }
    float inv = 1.0f / red[0];
#pragma unroll
    for (int q = 0; q < 9; q++)
        g_probs[(c * 1152 + tid + q * 128) * 16 + i] = e[q] * inv;
}

// ---------------------------------------------------------------------------
// s partial GEMM: grid (16 n-chunks of 72, 10 classes), 128 threads.
// Thread (ig,bg): 4 i's x 8 b's (b = bg + 32*bi, conflict-free smem reads).
// ---------------------------------------------------------------------------
__global__ __launch_bounds__(128) void sgemm_routing_kernel(const float* __restrict__ W) {
    int nc = blockIdx.x, c = blockIdx.y;
    int tid = threadIdx.x;
    int ig = tid >> 5, bg = tid & 31;
    int i0 = ig << 2;
    __shared__ float uu[2048];  // [j][b] for current n
    __shared__ float pw[128];   // probs*W for current n
    int pi = tid >> 3, pj = tid & 7;

    float acc[4][8];
#pragma unroll
    for (int ii = 0; ii < 4; ii++)
#pragma unroll
        for (int bi = 0; bi < 8; bi++) acc[ii][bi] = 0.f;

    for (int n = nc * 72; n < nc * 72 + 72; ++n) {
        __syncthreads();
        const float4* src = (const float4*)&g_uT[n * 2048];
#pragma unroll
        for (int q = 0; q < 4; q++) ((float4*)uu)[tid + q * 128] = src[tid + q * 128];
        pw[tid] = g_probs[(c * 1152 + n) * 16 + pi] *
                  W[((c * 1152 + n) * 16 + pi) * 8 + pj];
        __syncthreads();

        float pwv[4][8];
#pragma unroll
        for (int ii = 0; ii < 4; ii++)
#pragma unroll
            for (int j = 0; j < 8; j++) pwv[ii][j] = pw[(i0 + ii) * 8 + j];

#pragma unroll
        for (int bi = 0; bi < 8; bi++) {
            int b = bg + (bi << 5);
            float uv[8];
#pragma unroll
            for (int j = 0; j < 8; j++) uv[j] = uu[j * 256 + b];
#pragma unroll
            for (int ii = 0; ii < 4; ii++)
#pragma unroll
                for (int j = 0; j < 8; j++)
                    acc[ii][bi] = fmaf(pwv[ii][j], uv[j], acc[ii][bi]);
        }
    }
#pragma unroll
    for (int ii = 0; ii < 4; ii++)
#pragma unroll
        for (int bi = 0; bi < 8; bi++)
            g_spart[((c * 16 + nc) * 16 + i0 + ii) * 256 + bg + (bi << 5)] = acc[ii][bi];
}

// ---------------------------------------------------------------------------
// reduce partials + routing squash over BATCH axis -> v[c][i][b]
// ---------------------------------------------------------------------------
__global__ __launch_bounds__(256) void squashv_kernel() {
    int c = blockIdx.x >> 4, i = blockIdx.x & 15;
    int tid = threadIdx.x;  // = b
    float sv = 0.f;
#pragma unroll
    for (int ch = 0; ch < 16; ch++)
        sv += g_spart[((c * 16 + ch) * 16 + i) * 256 + tid];
    __shared__ float red[256];
    red[tid] = sv * sv;
    __syncthreads();
    for (int s2 = 128; s2 > 0; s2 >>= 1) {
        if (tid < s2) red[tid] += red[tid + s2];
        __syncthreads();
    }
    float sq = red[0];
    float scale = sq / ((1.0f + sq) * sqrtf(sq));
    g_v[(c * 16 + i) * 256 + tid] = sv * scale;
}

// ---------------------------------------------------------------------------
// delta_b accumulation: grid (144 n-chunks of 8, 10 classes), 128 threads
// thread = (nl, i); recomputes u_hat on the fly from W and uT.
// ---------------------------------------------------------------------------
__global__ __launch_bounds__(128) void delta_kernel(const float* __restrict__ W) {
    int n0 = blockIdx.x * 8, c = blockIdx.y;
    int tid = threadIdx.x;
    int nl = tid >> 4, i = tid & 15;
    int n = n0 + nl;
    __shared__ float vsh[16 * 257];  // padded, bank-conflict free across i
    __shared__ float ush[2048];      // [r=nl*8+j][bb]
    float wr[8];
    const float* wp = &W[((c * 1152 + n) * 16 + i) * 8];
#pragma unroll
    for (int j = 0; j < 8; j++) wr[j] = wp[j];
#pragma unroll
    for (int q = 0; q < 32; q++) {
        int idx = tid + q * 128;
        vsh[(idx >> 8) * 257 + (idx & 255)] = g_v[c * 4096 + idx];
    }
    float acc = 0.f;
    for (int bc = 0; bc < 8; bc++) {
        __syncthreads();
#pragma unroll
        for (int q = 0; q < 16; q++) {
            int f = tid + q * 128;
            ush[f] = g_uT[(n0 * 8 + (f >> 5)) * 256 + (bc << 5) + (f & 31)];
        }
        __syncthreads();
#pragma unroll 4
        for (int bb = 0; bb < 32; bb++) {
            int b = (bc << 5) + bb;
            float uh = 0.f;
#pragma unroll
            for (int j = 0; j < 8; j++)
                uh = fmaf(wr[j], ush[(nl * 8 + j) * 32 + bb], uh);
            acc = fmaf(uh, vsh[i * 257 + b], acc);
        }
    }
    g_blog[(c * 1152 + n) * 16 + i] += acc;
}

// ---------------------------------------------------------------------------
// out[b,c] = sum_i v[c,i,b]^2
// ---------------------------------------------------------------------------
__global__ void out_kernel(float* __restrict__ out) {
    int c = blockIdx.x, b = threadIdx.x;
    float s = 0.f;
#pragma unroll
    for (int i = 0; i < 16; i++) {
        float t = g_v[(c * 16 + i) * 256 + b];
        s = fmaf(t, t, s);
    }
    out[b * 10 + c] = s;
}

// ---------------------------------------------------------------------------
extern "C" void kernel_launch(void* const* d_in, const int* in_sizes, int n_in,
                              void* d_out, int out_size) {
    const float* x  = (const float*)d_in[0];
    const float* w1 = (const float*)d_in[1];
    const float* b1 = (const float*)d_in[2];
    const float* w2 = (const float*)d_in[3];
    const float* b2 = (const float*)d_in[4];
    const float* W  = (const float*)d_in[5];
    float* out = (float*)d_out;

    conv1_kernel<<<dim3(256, 16), 128>>>(x, w1, b1);
    conv2_kernel<<<dim3(2, 72), 256>>>(w2, b2);
    squashT_kernel<<<1152, 256>>>();
    zero_blog_kernel<<<720, 256>>>();

    for (int it = 0; it < 3; it++) {
        softmax_kernel<<<160, 128>>>();
        sgemm_routing_kernel<<<dim3(16, 10), 128>>>(W);
        squashv_kernel<<<160, 256>>>();
        if (it < 2) delta_kernel<<<dim3(144, 10), 128>>>(W);
    }
    out_kernel<<<10, 256>>>(out);
}

// round 6
// speedup vs baseline: 2.1167x; 2.1167x over previous
#include <cuda_runtime.h>
#include <cuda_bf16.h>
#include <math.h>
#include <stdint.h>

// ===========================================================================
// Baseline-PTX helpers only (sm_80-level: ldmatrix + mma.sync). No tcgen05 —
// harness targets plain sm_100, arch-suffix features unavailable.
// ===========================================================================
__device__ __forceinline__ uint32_t smem_u32(const void* p) {
    uint32_t a;
    asm("{ .reg .u64 t; cvta.to.shared.u64 t, %1; cvt.u32.u64 %0, t; }" : "=r"(a) : "l"(p));
    return a;
}
__device__ __forceinline__ void ldsm_x4(uint32_t r[4], uint32_t addr) {
    asm volatile("ldmatrix.sync.aligned.m8n8.x4.shared.b16 {%0,%1,%2,%3}, [%4];"
                 : "=r"(r[0]), "=r"(r[1]), "=r"(r[2]), "=r"(r[3]) : "r"(addr));
}
__device__ __forceinline__ void mma16816(float c[4], const uint32_t a[4],
                                         uint32_t b0, uint32_t b1) {
    asm volatile(
        "mma.sync.aligned.m16n8k16.row.col.f32.bf16.bf16.f32 "
        "{%0,%1,%2,%3}, {%4,%5,%6,%7}, {%8,%9}, {%0,%1,%2,%3};"
        : "+f"(c[0]), "+f"(c[1]), "+f"(c[2]), "+f"(c[3])
        : "r"(a[0]), "r"(a[1]), "r"(a[2]), "r"(a[3]), "r"(b0), "r"(b1));
}

// ===========================================================================
// Scratch (device globals)
// ===========================================================================
__device__ float g_h1[256 * 256 * 400];
__device__ float g_uraw[256 * 9216];
__device__ float g_uT[9216 * 256];
__device__ float g_blog[10 * 1152 * 16];
__device__ float g_probs[10 * 1152 * 16];
__device__ float g_spart[10 * 16 * 16 * 256];
__device__ float g_v[10 * 16 * 256];
__device__ __nv_bfloat16 g_w2hi[256 * 20736];
__device__ __nv_bfloat16 g_w2lo[256 * 20736];

// ===========================================================================
// conv1 (unchanged, known-good)
// ===========================================================================
__global__ __launch_bounds__(128) void conv1_kernel(const float* __restrict__ x,
                                                    const float* __restrict__ w,
                                                    const float* __restrict__ bias) {
    int b = blockIdx.x, ocg = blockIdx.y;
    __shared__ float xs[784];
    __shared__ float ws[16 * 81];
    int tid = threadIdx.x;
    for (int i = tid; i < 784; i += 128) xs[i] = x[b * 784 + i];
    for (int i = tid; i < 1296; i += 128) ws[i] = w[ocg * 1296 + i];
    __syncthreads();

    int pr[4], pc[4];
    bool val[4];
#pragma unroll
    for (int q = 0; q < 4; q++) {
        int p = tid + q * 128;
        val[q] = (p < 400);
        int pp = val[q] ? p : 0;
        pr[q] = pp / 20;
        pc[q] = pp % 20;
    }
    float acc[4][16];
#pragma unroll
    for (int q = 0; q < 4; q++)
#pragma unroll
        for (int o = 0; o < 16; o++) acc[q][o] = 0.f;

#pragma unroll 1
    for (int kh = 0; kh < 9; kh++) {
        int rb[4];
#pragma unroll
        for (int q = 0; q < 4; q++) rb[q] = (pr[q] + kh) * 28 + pc[q];
#pragma unroll 1
        for (int kw = 0; kw < 9; kw++) {
            float xv[4];
#pragma unroll
            for (int q = 0; q < 4; q++) xv[q] = xs[rb[q] + kw];
            int ko = kh * 9 + kw;
#pragma unroll
            for (int o = 0; o < 16; o++) {
                float wv = ws[o * 81 + ko];
#pragma unroll
                for (int q = 0; q < 4; q++) acc[q][o] = fmaf(xv[q], wv, acc[q][o]);
            }
        }
    }
#pragma unroll
    for (int o = 0; o < 16; o++) {
        float bv = bias[ocg * 16 + o];
#pragma unroll
        for (int q = 0; q < 4; q++) {
            if (val[q]) {
                float v = acc[q][o] + bv;
                g_h1[(b * 256 + ocg * 16 + o) * 400 + tid + q * 128] = fmaxf(v, 0.f);
            }
        }
    }
}

// ===========================================================================
// w2 fp32 -> bf16 hi/lo split planes
// ===========================================================================
__global__ __launch_bounds__(256) void w2prep_kernel(const float* __restrict__ w2) {
    int i = blockIdx.x * 256 + threadIdx.x;
    if (i < 256 * 20736) {
        float v = w2[i];
        __nv_bfloat16 hi = __float2bfloat16(v);
        __nv_bfloat16 lo = __float2bfloat16(v - __bfloat162float(hi));
        g_w2hi[i] = hi;
        g_w2lo[i] = lo;
    }
}

// ===========================================================================
// conv2 implicit GEMM on tensor cores (mma.sync m16n8k16 bf16, 3-term split):
// M=256(oc) x N=9216(b*36+s) x K=20736(ic*81); grid (2,72), 256 thr, 8 warps.
// BM=BN=128, BK=32; warp tile 32x64. smem rows padded to 80B (conflict-free
// ldmatrix). Register-prefetch of stage s+1 overlaps the MMA compute of s.
// B tiles stored [n][k] (k contiguous) -> NON-trans ldmatrix gives the
// correct col-operand fragment (consecutive-k pairs per thread).
// ===========================================================================
#define ROWB 80  // padded row stride in bytes (32 bf16 = 64B data + 16B pad)

__global__ __launch_bounds__(256, 1) void conv2_mma_kernel(const float* __restrict__ b2) {
    __shared__ __align__(16) unsigned char sm[4 * 128 * ROWB];  // Ahi|Alo|Bhi|Blo
    __shared__ int nAddr[128];

    const int tid = threadIdx.x, lane = tid & 31, wid = tid >> 5;
    const int m0 = blockIdx.x * 128, n0 = blockIdx.y * 128;
    const int wm0 = (wid & 3) * 32;       // warp m offset (4 warps over 128)
    const int wn0 = (wid >> 2) * 64;      // warp n offset (2 warps over 128)
    const uint32_t sb = smem_u32(sm);
    const uint32_t sAhi = sb, sAlo = sb + 10240, sBhi = sb + 20480, sBlo = sb + 30720;

    if (tid < 128) {
        int n = n0 + tid;
        int bb = n / 36, s = n - bb * 36;
        nAddr[tid] = bb * 102400 + (s / 6) * 40 + (s % 6) * 2;
    }
    __syncthreads();

    float acc[2][8][4];
#pragma unroll
    for (int mi = 0; mi < 2; mi++)
#pragma unroll
        for (int nt = 0; nt < 8; nt++)
#pragma unroll
            for (int q = 0; q < 4; q++) acc[mi][nt][q] = 0.f;

    // per-thread fetch roles
    const int kp = tid & 15;   // B k-pair (k = 2kp, 2kp+1) within BK=32
    const int nr = tid >> 4;   // B n start (0..15)

    uint4 aval[4];
    float bval[16];

    // ---- fetch stage kt into registers ----
    auto fetch = [&](int kt) {
#pragma unroll
        for (int q = 0; q < 4; q++) {
            int id = q * 256 + tid;      // 1024 16B-chunks: 2 planes x 128 rows x 4
            int plane = id >> 9;
            int rem = id & 511;
            int row = rem >> 2;
            int c16 = rem & 3;
            const __nv_bfloat16* src = plane ? g_w2lo : g_w2hi;
            aval[q] = *(const uint4*)&src[(size_t)(m0 + row) * 20736 + kt + c16 * 8];
        }
        int kg0 = kt + kp * 2;
        int ic0 = kg0 / 81, rr0 = kg0 - ic0 * 81;
        int koff0 = ic0 * 400 + (rr0 / 9) * 20 + (rr0 % 9);
        int kg1 = kg0 + 1;
        int ic1 = kg1 / 81, rr1 = kg1 - ic1 * 81;
        int koff1 = ic1 * 400 + (rr1 / 9) * 20 + (rr1 % 9);
#pragma unroll
        for (int q = 0; q < 8; q++) {
            int base = nAddr[q * 16 + nr];
            bval[2 * q] = g_h1[base + koff0];
            bval[2 * q + 1] = g_h1[base + koff1];
        }
    };

    fetch(0);
    for (int s = 0; s < 648; s++) {
        __syncthreads();  // previous compute done; smem free
        // ---- store registers -> smem tiles ----
#pragma unroll
        for (int q = 0; q < 4; q++) {
            int id = q * 256 + tid;
            int plane = id >> 9;
            int rem = id & 511;
            int row = rem >> 2;
            int c16 = rem & 3;
            *(uint4*)(sm + plane * 10240 + row * ROWB + c16 * 16) = aval[q];
        }
#pragma unroll
        for (int q = 0; q < 8; q++) {
            int n = q * 16 + nr;
            float v0 = bval[2 * q], v1 = bval[2 * q + 1];
            __nv_bfloat16 h0 = __float2bfloat16(v0);
            __nv_bfloat16 h1 = __float2bfloat16(v1);
            __nv_bfloat16 l0 = __float2bfloat16(v0 - __bfloat162float(h0));
            __nv_bfloat16 l1 = __float2bfloat16(v1 - __bfloat162float(h1));
            *(__nv_bfloat162*)(sm + 20480 + n * ROWB + kp * 4) = __halves2bfloat162(h0, h1);
            *(__nv_bfloat162*)(sm + 30720 + n * ROWB + kp * 4) = __halves2bfloat162(l0, l1);
        }
        __syncthreads();
        if (s + 1 < 648) fetch((s + 1) * 32);  // loads overlap compute below

        // ---- compute: 2 k-steps x (2m x 8n) x 3 terms = 96 MMAs/warp ----
#pragma unroll
        for (int ks = 0; ks < 2; ks++) {
            uint32_t ah[2][4], al[2][4];
#pragma unroll
            for (int mi = 0; mi < 2; mi++) {
                uint32_t ra = (uint32_t)((wm0 + mi * 16 + (lane & 15)) * ROWB +
                                         ks * 32 + ((lane >> 4) << 4));
                ldsm_x4(ah[mi], sAhi + ra);
                ldsm_x4(al[mi], sAlo + ra);
            }
            // B: rows = n, cols = k. NON-trans ldmatrix -> correct col fragment.
            // r0 = n0-7/k0-7, r1 = n0-7/k8-15, r2 = n8-15/k0-7, r3 = n8-15/k8-15
            uint32_t bh[4][4], bl[4][4];
#pragma unroll
            for (int g = 0; g < 4; g++) {
                uint32_t rb = (uint32_t)((wn0 + g * 16 + (lane & 7) + ((lane >> 4) << 3)) * ROWB +
                                         ks * 32 + (((lane >> 3) & 1) << 4));
                ldsm_x4(bh[g], sBhi + rb);
                ldsm_x4(bl[g], sBlo + rb);
            }
#pragma unroll
            for (int mi = 0; mi < 2; mi++)
#pragma unroll
                for (int g = 0; g < 4; g++)
#pragma unroll
                    for (int h = 0; h < 2; h++) {
                        int nt = g * 2 + h;
                        mma16816(acc[mi][nt], ah[mi], bh[g][2 * h], bh[g][2 * h + 1]);
                        mma16816(acc[mi][nt], ah[mi], bl[g][2 * h], bl[g][2 * h + 1]);
                        mma16816(acc[mi][nt], al[mi], bh[g][2 * h], bh[g][2 * h + 1]);
                    }
        }
    }

    // ---- epilogue: fragment scatter + bias into u_raw layout ----
#pragma unroll
    for (int mi = 0; mi < 2; mi++) {
        int r0 = m0 + wm0 + mi * 16 + (lane >> 2);
        int r1 = r0 + 8;
        float bias0 = b2[r0], bias1 = b2[r1];
#pragma unroll
        for (int nt = 0; nt < 8; nt++) {
            int c0 = n0 + wn0 + nt * 8 + ((lane & 3) << 1);
            int c1 = c0 + 1;
            int bb0 = c0 / 36, ss0 = c0 - bb0 * 36;
            int bb1 = c1 / 36, ss1 = c1 - bb1 * 36;
            g_uraw[bb0 * 9216 + ss0 + r0 * 36] = acc[mi][nt][0] + bias0;
            g_uraw[bb1 * 9216 + ss1 + r0 * 36] = acc[mi][nt][1] + bias0;
            g_uraw[bb0 * 9216 + ss0 + r1 * 36] = acc[mi][nt][2] + bias1;
            g_uraw[bb1 * 9216 + ss1 + r1 * 36] = acc[mi][nt][3] + bias1;
        }
    }
}

// ===========================================================================
// primary squash + transpose
// ===========================================================================
__global__ __launch_bounds__(256) void squashT_kernel() {
    int idx = blockIdx.x * 256 + threadIdx.x;
    int n = idx >> 8, b = idx & 255;
    const float4* src = (const float4*)&g_uraw[b * 9216 + n * 8];
    float4 u0 = src[0], u1 = src[1];
    float sq = u0.x * u0.x + u0.y * u0.y + u0.z * u0.z + u0.w * u0.w +
               u1.x * u1.x + u1.y * u1.y + u1.z * u1.z + u1.w * u1.w;
    float sc = sq / (1.0f + sq);
    float r[8] = {u0.x * sc, u0.y * sc, u0.z * sc, u0.w * sc,
                  u1.x * sc, u1.y * sc, u1.z * sc, u1.w * sc};
#pragma unroll
    for (int j = 0; j < 8; j++) g_uT[(n * 8 + j) * 256 + b] = r[j];
}

__global__ void zero_blog_kernel() {
    int i = blockIdx.x * 256 + threadIdx.x;
    if (i < 184320) g_blog[i] = 0.f;
}

__global__ __launch_bounds__(128) void softmax_kernel() {
    int c = blockIdx.x >> 4, i = blockIdx.x & 15;
    int tid = threadIdx.x;
    __shared__ float red[128];
    float vals[9];
    float m = -1e30f;
#pragma unroll
    for (int q = 0; q < 9; q++) {
        int n = tid + q * 128;
        vals[q] = g_blog[(c * 1152 + n) * 16 + i];
        m = fmaxf(m, vals[q]);
    }
    red[tid] = m;
    __syncthreads();
    for (int s2 = 64; s2 > 0; s2 >>= 1) {
        if (tid < s2) red[tid] = fmaxf(red[tid], red[tid + s2]);
        __syncthreads();
    }
    float M = red[0];
    __syncthreads();
    float e[9];
    float sum = 0.f;
#pragma unroll
    for (int q = 0; q < 9; q++) {
        e[q] = expf(vals[q] - M);
        sum += e[q];
    }
    red[tid] = sum;
    __syncthreads();
    for (int s2 = 64; s2 > 0; s2 >>= 1) {
        if (tid < s2) red[tid] += red[tid + s2];
        __syncthreads();
    }
    float inv = 1.0f / red[0];
#pragma unroll
    for (int q = 0; q < 9; q++)
        g_probs[(c * 1152 + tid + q * 128) * 16 + i] = e[q] * inv;
}

__global__ __launch_bounds__(128) void sgemm_routing_kernel(const float* __restrict__ W) {
    int nc = blockIdx.x, c = blockIdx.y;
    int tid = threadIdx.x;
    int ig = tid >> 5, bg = tid & 31;
    int i0 = ig << 2;
    __shared__ float uu[2048];
    __shared__ float pw[128];
    int pi = tid >> 3, pj = tid & 7;

    float acc[4][8];
#pragma unroll
    for (int ii = 0; ii < 4; ii++)
#pragma unroll
        for (int bi = 0; bi < 8; bi++) acc[ii][bi] = 0.f;

    for (int n = nc * 72; n < nc * 72 + 72; ++n) {
        __syncthreads();
        const float4* src = (const float4*)&g_uT[n * 2048];
#pragma unroll
        for (int q = 0; q < 4; q++) ((float4*)uu)[tid + q * 128] = src[tid + q * 128];
        pw[tid] = g_probs[(c * 1152 + n) * 16 + pi] *
                  W[((c * 1152 + n) * 16 + pi) * 8 + pj];
        __syncthreads();

        float pwv[4][8];
#pragma unroll
        for (int ii = 0; ii < 4; ii++)
#pragma unroll
            for (int j = 0; j < 8; j++) pwv[ii][j] = pw[(i0 + ii) * 8 + j];

#pragma unroll
        for (int bi = 0; bi < 8; bi++) {
            int b = bg + (bi << 5);
            float uv[8];
#pragma unroll
            for (int j = 0; j < 8; j++) uv[j] = uu[j * 256 + b];
#pragma unroll
            for (int ii = 0; ii < 4; ii++)
#pragma unroll
                for (int j = 0; j < 8; j++)
                    acc[ii][bi] = fmaf(pwv[ii][j], uv[j], acc[ii][bi]);
        }
    }
#pragma unroll
    for (int ii = 0; ii < 4; ii++)
#pragma unroll
        for (int bi = 0; bi < 8; bi++)
            g_spart[((c * 16 + nc) * 16 + i0 + ii) * 256 + bg + (bi << 5)] = acc[ii][bi];
}

__global__ __launch_bounds__(256) void squashv_kernel() {
    int c = blockIdx.x >> 4, i = blockIdx.x & 15;
    int tid = threadIdx.x;
    float sv = 0.f;
#pragma unroll
    for (int ch = 0; ch < 16; ch++)
        sv += g_spart[((c * 16 + ch) * 16 + i) * 256 + tid];
    __shared__ float red[256];
    red[tid] = sv * sv;
    __syncthreads();
    for (int s2 = 128; s2 > 0; s2 >>= 1) {
        if (tid < s2) red[tid] += red[tid + s2];
        __syncthreads();
    }
    float sq = red[0];
    float scale = sq / ((1.0f + sq) * sqrtf(sq));
    g_v[(c * 16 + i) * 256 + tid] = sv * scale;
}

__global__ __launch_bounds__(128) void delta_kernel(const float* __restrict__ W) {
    int n0 = blockIdx.x * 8, c = blockIdx.y;
    int tid = threadIdx.x;
    int nl = tid >> 4, i = tid & 15;
    int n = n0 + nl;
    __shared__ float vsh[16 * 257];
    __shared__ float ush[2048];
    float wr[8];
    const float* wp = &W[((c * 1152 + n) * 16 + i) * 8];
#pragma unroll
    for (int j = 0; j < 8; j++) wr[j] = wp[j];
#pragma unroll
    for (int q = 0; q < 32; q++) {
        int idx = tid + q * 128;
        vsh[(idx >> 8) * 257 + (idx & 255)] = g_v[c * 4096 + idx];
    }
    float acc = 0.f;
    for (int bc = 0; bc < 8; bc++) {
        __syncthreads();
#pragma unroll
        for (int q = 0; q < 16; q++) {
            int f = tid + q * 128;
            ush[f] = g_uT[(n0 * 8 + (f >> 5)) * 256 + (bc << 5) + (f & 31)];
        }
        __syncthreads();
#pragma unroll 4
        for (int bb = 0; bb < 32; bb++) {
            int b = (bc << 5) + bb;
            float uh = 0.f;
#pragma unroll
            for (int j = 0; j < 8; j++)
                uh = fmaf(wr[j], ush[(nl * 8 + j) * 32 + bb], uh);
            acc = fmaf(uh, vsh[i * 257 + b], acc);
        }
    }
    g_blog[(c * 1152 + n) * 16 + i] += acc;
}

__global__ void out_kernel(float* __restrict__ out) {
    int c = blockIdx.x, b = threadIdx.x;
    float s = 0.f;
#pragma unroll
    for (int i = 0; i < 16; i++) {
        float t = g_v[(c * 16 + i) * 256 + b];
        s = fmaf(t, t, s);
    }
    out[b * 10 + c] = s;
}

// ===========================================================================
extern "C" void kernel_launch(void* const* d_in, const int* in_sizes, int n_in,
                              void* d_out, int out_size) {
    const float* x  = (const float*)d_in[0];
    const float* w1 = (const float*)d_in[1];
    const float* b1 = (const float*)d_in[2];
    const float* w2 = (const float*)d_in[3];
    const float* b2 = (const float*)d_in[4];
    const float* W  = (const float*)d_in[5];
    float* out = (float*)d_out;

    conv1_kernel<<<dim3(256, 16), 128>>>(x, w1, b1);
    w2prep_kernel<<<(256 * 20736 + 255) / 256, 256>>>(w2);
    conv2_mma_kernel<<<dim3(2, 72), 256>>>(b2);
    squashT_kernel<<<1152, 256>>>();
    zero_blog_kernel<<<720, 256>>>();

    for (int it = 0; it < 3; it++) {
        softmax_kernel<<<160, 128>>>();
        sgemm_routing_kernel<<<dim3(16, 10), 128>>>(W);
        squashv_kernel<<<160, 256>>>();
        if (it < 2) delta_kernel<<<dim3(144, 10), 128>>>(W);
    }
    out_kernel<<<10, 256>>>(out);
}

// round 7
// speedup vs baseline: 2.2015x; 1.0401x over previous
#include <cuda_runtime.h>
#include <cuda_bf16.h>
#include <math.h>
#include <stdint.h>

// ===========================================================================
// Baseline-PTX helpers (sm_80-level: ldmatrix + mma.sync + cp.async).
// No tcgen05 — harness targets plain sm_100.
// ===========================================================================
__device__ __forceinline__ uint32_t smem_u32(const void* p) {
    uint32_t a;
    asm("{ .reg .u64 t; cvta.to.shared.u64 t, %1; cvt.u32.u64 %0, t; }" : "=r"(a) : "l"(p));
    return a;
}
__device__ __forceinline__ void ldsm_x4(uint32_t r[4], uint32_t addr) {
    asm volatile("ldmatrix.sync.aligned.m8n8.x4.shared.b16 {%0,%1,%2,%3}, [%4];"
                 : "=r"(r[0]), "=r"(r[1]), "=r"(r[2]), "=r"(r[3]) : "r"(addr));
}
__device__ __forceinline__ void mma16816(float c[4], const uint32_t a[4],
                                         uint32_t b0, uint32_t b1) {
    asm volatile(
        "mma.sync.aligned.m16n8k16.row.col.f32.bf16.bf16.f32 "
        "{%0,%1,%2,%3}, {%4,%5,%6,%7}, {%8,%9}, {%0,%1,%2,%3};"
        : "+f"(c[0]), "+f"(c[1]), "+f"(c[2]), "+f"(c[3])
        : "r"(a[0]), "r"(a[1]), "r"(a[2]), "r"(a[3]), "r"(b0), "r"(b1));
}
__device__ __forceinline__ void cp16(uint32_t dst, const void* src) {
    asm volatile("cp.async.cg.shared.global [%0], [%1], 16;" ::"r"(dst), "l"(src));
}
#define CP_COMMIT() asm volatile("cp.async.commit_group;" ::: "memory")
#define CP_WAIT0() asm volatile("cp.async.wait_group 0;" ::: "memory")

// ===========================================================================
// Scratch (device globals)
// ===========================================================================
__device__ float g_h1[256 * 256 * 400];
__device__ float g_uraw[256 * 9216];
__device__ float g_uT[9216 * 256];
__device__ float g_blog[10 * 1152 * 16];
__device__ float g_probs[10 * 1152 * 16];
__device__ float g_spart[10 * 16 * 16 * 256];
__device__ float g_v[10 * 16 * 256];
__device__ __nv_bfloat16 g_w2hi[256 * 20736];
__device__ __nv_bfloat16 g_w2lo[256 * 20736];

// ===========================================================================
// conv1 (unchanged, known-good)
// ===========================================================================
__global__ __launch_bounds__(128) void conv1_kernel(const float* __restrict__ x,
                                                    const float* __restrict__ w,
                                                    const float* __restrict__ bias) {
    int b = blockIdx.x, ocg = blockIdx.y;
    __shared__ float xs[784];
    __shared__ float ws[16 * 81];
    int tid = threadIdx.x;
    for (int i = tid; i < 784; i += 128) xs[i] = x[b * 784 + i];
    for (int i = tid; i < 1296; i += 128) ws[i] = w[ocg * 1296 + i];
    __syncthreads();

    int pr[4], pc[4];
    bool val[4];
#pragma unroll
    for (int q = 0; q < 4; q++) {
        int p = tid + q * 128;
        val[q] = (p < 400);
        int pp = val[q] ? p : 0;
        pr[q] = pp / 20;
        pc[q] = pp % 20;
    }
    float acc[4][16];
#pragma unroll
    for (int q = 0; q < 4; q++)
#pragma unroll
        for (int o = 0; o < 16; o++) acc[q][o] = 0.f;

#pragma unroll 1
    for (int kh = 0; kh < 9; kh++) {
        int rb[4];
#pragma unroll
        for (int q = 0; q < 4; q++) rb[q] = (pr[q] + kh) * 28 + pc[q];
#pragma unroll 1
        for (int kw = 0; kw < 9; kw++) {
            float xv[4];
#pragma unroll
            for (int q = 0; q < 4; q++) xv[q] = xs[rb[q] + kw];
            int ko = kh * 9 + kw;
#pragma unroll
            for (int o = 0; o < 16; o++) {
                float wv = ws[o * 81 + ko];
#pragma unroll
                for (int q = 0; q < 4; q++) acc[q][o] = fmaf(xv[q], wv, acc[q][o]);
            }
        }
    }
#pragma unroll
    for (int o = 0; o < 16; o++) {
        float bv = bias[ocg * 16 + o];
#pragma unroll
        for (int q = 0; q < 4; q++) {
            if (val[q]) {
                float v = acc[q][o] + bv;
                g_h1[(b * 256 + ocg * 16 + o) * 400 + tid + q * 128] = fmaxf(v, 0.f);
            }
        }
    }
}

// ===========================================================================
// w2 fp32 -> bf16 hi/lo split planes
// ===========================================================================
__global__ __launch_bounds__(256) void w2prep_kernel(const float* __restrict__ w2) {
    int i = blockIdx.x * 256 + threadIdx.x;
    if (i < 256 * 20736) {
        float v = w2[i];
        __nv_bfloat16 hi = __float2bfloat16(v);
        __nv_bfloat16 lo = __float2bfloat16(v - __bfloat162float(hi));
        g_w2hi[i] = hi;
        g_w2lo[i] = lo;
    }
}

// ===========================================================================
// conv2 implicit GEMM (mma.sync bf16, 3-term split), BK=64, double-buffered:
// M=256 x N=9216 x K=20736; grid (2,72), 256 thr / 8 warps; warp tile 32x64.
// A planes (pre-split bf16) via cp.async global->smem; B gathered fp32,
// split in-regs, stored into the NEXT buffer after compute (latency hidden).
// One __syncthreads per stage. ROWB=144 -> conflict-free ldsm / B stores.
// ===========================================================================
#define ROWB 144
#define PLANE (128 * ROWB)   // 18432
#define BUFSZ (4 * PLANE)    // 73728 (Ahi|Alo|Bhi|Blo)
#define NSTAGE 324

__global__ __launch_bounds__(256, 1) void conv2_mma_kernel(const float* __restrict__ b2) {
    extern __shared__ __align__(16) unsigned char sm[];
    __shared__ int nAddr[128];

    const int tid = threadIdx.x, lane = tid & 31, wid = tid >> 5;
    const int m0 = blockIdx.x * 128, n0 = blockIdx.y * 128;
    const int wm0 = (wid & 3) * 32;
    const int wn0 = (wid >> 2) * 64;
    const uint32_t sb = smem_u32(sm);

    if (tid < 128) {
        int n = n0 + tid;
        int bb = n / 36, s = n - bb * 36;
        nAddr[tid] = bb * 102400 + (s / 6) * 40 + (s % 6) * 2;
    }
    __syncthreads();

    float acc[2][8][4];
#pragma unroll
    for (int mi = 0; mi < 2; mi++)
#pragma unroll
        for (int nt = 0; nt < 8; nt++)
#pragma unroll
            for (int q = 0; q < 4; q++) acc[mi][nt][q] = 0.f;

    const int kp = tid & 31;   // B k-pair (k = 2kp, 2kp+1) within BK=64
    const int nr = tid >> 5;   // B n start (0..7)
    float bval[32];

    // ---- A: 2 planes x 128 rows x 4x16B chunks -> cp.async ----
    auto issueA = [&](uint32_t base, int kt) {
#pragma unroll
        for (int q = 0; q < 8; q++) {
            int id = q * 256 + tid;
            int plane = id >> 10;
            int rem = id & 1023;
            int row = rem >> 3;
            int c16 = rem & 7;
            const __nv_bfloat16* src = plane ? g_w2lo : g_w2hi;
            cp16(base + plane * PLANE + row * ROWB + c16 * 16,
                 &src[(size_t)(m0 + row) * 20736 + kt + c16 * 8]);
        }
        CP_COMMIT();
    };
    // ---- B: gather 32 fp32 values (16 n's x 2 k's) into regs ----
    auto fetchB = [&](int kt) {
        int kg0 = kt + kp * 2;
        int ic0 = kg0 / 81, rr0 = kg0 - ic0 * 81;
        int koff0 = ic0 * 400 + (rr0 / 9) * 20 + (rr0 % 9);
        int kg1 = kg0 + 1;
        int ic1 = kg1 / 81, rr1 = kg1 - ic1 * 81;
        int koff1 = ic1 * 400 + (rr1 / 9) * 20 + (rr1 % 9);
#pragma unroll
        for (int q = 0; q < 16; q++) {
            int base = nAddr[q * 8 + nr];
            bval[2 * q] = g_h1[base + koff0];
            bval[2 * q + 1] = g_h1[base + koff1];
        }
    };
    // ---- B: split + store into buffer (conflict-free: banks=n*36+kp) ----
    auto storeB = [&](int buf) {
        unsigned char* bh = sm + buf * BUFSZ + 2 * PLANE;
        unsigned char* bl = sm + buf * BUFSZ + 3 * PLANE;
#pragma unroll
        for (int q = 0; q < 16; q++) {
            int n = q * 8 + nr;
            float v0 = bval[2 * q], v1 = bval[2 * q + 1];
            __nv_bfloat16 h0 = __float2bfloat16(v0);
            __nv_bfloat16 h1 = __float2bfloat16(v1);
            __nv_bfloat16 l0 = __float2bfloat16(v0 - __bfloat162float(h0));
            __nv_bfloat16 l1 = __float2bfloat16(v1 - __bfloat162float(h1));
            *(__nv_bfloat162*)(bh + n * ROWB + kp * 4) = __halves2bfloat162(h0, h1);
            *(__nv_bfloat162*)(bl + n * ROWB + kp * 4) = __halves2bfloat162(l0, l1);
        }
    };

    // ---- prologue: stage 0 into buffer 0 ----
    issueA(sb, 0);
    fetchB(0);
    storeB(0);

    for (int s = 0; s < NSTAGE; s++) {
        const int cur = s & 1;
        const uint32_t cb = sb + cur * BUFSZ;
        CP_WAIT0();       // A(cur) arrived
        __syncthreads();  // B(cur) visible; all warps done with buffer cur^1

        if (s + 1 < NSTAGE) {
            issueA(sb + (cur ^ 1) * BUFSZ, (s + 1) * 64);
            fetchB((s + 1) * 64);  // LDGs overlap the MMA block below
        }

        // ---- compute: 4 k-steps x (2m x 8n) x 3 terms = 192 MMAs/warp ----
#pragma unroll
        for (int ks = 0; ks < 4; ks++) {
            uint32_t ah[2][4], al[2][4];
#pragma unroll
            for (int mi = 0; mi < 2; mi++) {
                uint32_t ra = (uint32_t)((wm0 + mi * 16 + (lane & 15)) * ROWB +
                                         ks * 32 + ((lane >> 4) << 4));
                ldsm_x4(ah[mi], cb + ra);
                ldsm_x4(al[mi], cb + PLANE + ra);
            }
            uint32_t bh[4][4], bl[4][4];
#pragma unroll
            for (int g = 0; g < 4; g++) {
                uint32_t rb = (uint32_t)((wn0 + g * 16 + (lane & 7) + ((lane >> 4) << 3)) * ROWB +
                                         ks * 32 + (((lane >> 3) & 1) << 4));
                ldsm_x4(bh[g], cb + 2 * PLANE + rb);
                ldsm_x4(bl[g], cb + 3 * PLANE + rb);
            }
#pragma unroll
            for (int mi = 0; mi < 2; mi++)
#pragma unroll
                for (int g = 0; g < 4; g++)
#pragma unroll
                    for (int h = 0; h < 2; h++) {
                        int nt = g * 2 + h;
                        mma16816(acc[mi][nt], ah[mi], bh[g][2 * h], bh[g][2 * h + 1]);
                        mma16816(acc[mi][nt], ah[mi], bl[g][2 * h], bl[g][2 * h + 1]);
                        mma16816(acc[mi][nt], al[mi], bh[g][2 * h], bh[g][2 * h + 1]);
                    }
        }

        if (s + 1 < NSTAGE) storeB(cur ^ 1);  // LDG results landed during MMAs
    }

    // ---- epilogue: fragment scatter + bias into u_raw layout ----
#pragma unroll
    for (int mi = 0; mi < 2; mi++) {
        int r0 = m0 + wm0 + mi * 16 + (lane >> 2);
        int r1 = r0 + 8;
        float bias0 = b2[r0], bias1 = b2[r1];
#pragma unroll
        for (int nt = 0; nt < 8; nt++) {
            int c0 = n0 + wn0 + nt * 8 + ((lane & 3) << 1);
            int c1 = c0 + 1;
            int bb0 = c0 / 36, ss0 = c0 - bb0 * 36;
            int bb1 = c1 / 36, ss1 = c1 - bb1 * 36;
            g_uraw[bb0 * 9216 + ss0 + r0 * 36] = acc[mi][nt][0] + bias0;
            g_uraw[bb1 * 9216 + ss1 + r0 * 36] = acc[mi][nt][1] + bias0;
            g_uraw[bb0 * 9216 + ss0 + r1 * 36] = acc[mi][nt][2] + bias1;
            g_uraw[bb1 * 9216 + ss1 + r1 * 36] = acc[mi][nt][3] + bias1;
        }
    }
}

// ===========================================================================
// primary squash + transpose
// ===========================================================================
__global__ __launch_bounds__(256) void squashT_kernel() {
    int idx = blockIdx.x * 256 + threadIdx.x;
    int n = idx >> 8, b = idx & 255;
    const float4* src = (const float4*)&g_uraw[b * 9216 + n * 8];
    float4 u0 = src[0], u1 = src[1];
    float sq = u0.x * u0.x + u0.y * u0.y + u0.z * u0.z + u0.w * u0.w +
               u1.x * u1.x + u1.y * u1.y + u1.z * u1.z + u1.w * u1.w;
    float sc = sq / (1.0f + sq);
    float r[8] = {u0.x * sc, u0.y * sc, u0.z * sc, u0.w * sc,
                  u1.x * sc, u1.y * sc, u1.z * sc, u1.w * sc};
#pragma unroll
    for (int j = 0; j < 8; j++) g_uT[(n * 8 + j) * 256 + b] = r[j];
}

__global__ void zero_blog_kernel() {
    int i = blockIdx.x * 256 + threadIdx.x;
    if (i < 184320) g_blog[i] = 0.f;
}

__global__ __launch_bounds__(128) void softmax_kernel() {
    int c = blockIdx.x >> 4, i = blockIdx.x & 15;
    int tid = threadIdx.x;
    __shared__ float red[128];
    float vals[9];
    float m = -1e30f;
#pragma unroll
    for (int q = 0; q < 9; q++) {
        int n = tid + q * 128;
        vals[q] = g_blog[(c * 1152 + n) * 16 + i];
        m = fmaxf(m, vals[q]);
    }
    red[tid] = m;
    __syncthreads();
    for (int s2 = 64; s2 > 0; s2 >>= 1) {
        if (tid < s2) red[tid] = fmaxf(red[tid], red[tid + s2]);
        __syncthreads();
    }
    float M = red[0];
    __syncthreads();
    float e[9];
    float sum = 0.f;
#pragma unroll
    for (int q = 0; q < 9; q++) {
        e[q] = expf(vals[q] - M);
        sum += e[q];
    }
    red[tid] = sum;
    __syncthreads();
    for (int s2 = 64; s2 > 0; s2 >>= 1) {
        if (tid < s2) red[tid] += red[tid + s2];
        __syncthreads();
    }
    float inv = 1.0f / red[0];
#pragma unroll
    for (int q = 0; q < 9; q++)
        g_probs[(c * 1152 + tid + q * 128) * 16 + i] = e[q] * inv;
}

__global__ __launch_bounds__(128) void sgemm_routing_kernel(const float* __restrict__ W) {
    int nc = blockIdx.x, c = blockIdx.y;
    int tid = threadIdx.x;
    int ig = tid >> 5, bg = tid & 31;
    int i0 = ig << 2;
    __shared__ float uu[2048];
    __shared__ float pw[128];
    int pi = tid >> 3, pj = tid & 7;

    float acc[4][8];
#pragma unroll
    for (int ii = 0; ii < 4; ii++)
#pragma unroll
        for (int bi = 0; bi < 8; bi++) acc[ii][bi] = 0.f;

    for (int n = nc * 72; n < nc * 72 + 72; ++n) {
        __syncthreads();
        const float4* src = (const float4*)&g_uT[n * 2048];
#pragma unroll
        for (int q = 0; q < 4; q++) ((float4*)uu)[tid + q * 128] = src[tid + q * 128];
        pw[tid] = g_probs[(c * 1152 + n) * 16 + pi] *
                  W[((c * 1152 + n) * 16 + pi) * 8 + pj];
        __syncthreads();

        float pwv[4][8];
#pragma unroll
        for (int ii = 0; ii < 4; ii++)
#pragma unroll
            for (int j = 0; j < 8; j++) pwv[ii][j] = pw[(i0 + ii) * 8 + j];

#pragma unroll
        for (int bi = 0; bi < 8; bi++) {
            int b = bg + (bi << 5);
            float uv[8];
#pragma unroll
            for (int j = 0; j < 8; j++) uv[j] = uu[j * 256 + b];
#pragma unroll
            for (int ii = 0; ii < 4; ii++)
#pragma unroll
                for (int j = 0; j < 8; j++)
                    acc[ii][bi] = fmaf(pwv[ii][j], uv[j], acc[ii][bi]);
        }
    }
#pragma unroll
    for (int ii = 0; ii < 4; ii++)
#pragma unroll
        for (int bi = 0; bi < 8; bi++)
            g_spart[((c * 16 + nc) * 16 + i0 + ii) * 256 + bg + (bi << 5)] = acc[ii][bi];
}

__global__ __launch_bounds__(256) void squashv_kernel() {
    int c = blockIdx.x >> 4, i = blockIdx.x & 15;
    int tid = threadIdx.x;
    float sv = 0.f;
#pragma unroll
    for (int ch = 0; ch < 16; ch++)
        sv += g_spart[((c * 16 + ch) * 16 + i) * 256 + tid];
    __shared__ float red[256];
    red[tid] = sv * sv;
    __syncthreads();
    for (int s2 = 128; s2 > 0; s2 >>= 1) {
        if (tid < s2) red[tid] += red[tid + s2];
        __syncthreads();
    }
    float sq = red[0];
    float scale = sq / ((1.0f + sq) * sqrtf(sq));
    g_v[(c * 16 + i) * 256 + tid] = sv * scale;
}

__global__ __launch_bounds__(128) void delta_kernel(const float* __restrict__ W) {
    int n0 = blockIdx.x * 8, c = blockIdx.y;
    int tid = threadIdx.x;
    int nl = tid >> 4, i = tid & 15;
    int n = n0 + nl;
    __shared__ float vsh[16 * 257];
    __shared__ float ush[2048];
    float wr[8];
    const float* wp = &W[((c * 1152 + n) * 16 + i) * 8];
#pragma unroll
    for (int j = 0; j < 8; j++) wr[j] = wp[j];
#pragma unroll
    for (int q = 0; q < 32; q++) {
        int idx = tid + q * 128;
        vsh[(idx >> 8) * 257 + (idx & 255)] = g_v[c * 4096 + idx];
    }
    float acc = 0.f;
    for (int bc = 0; bc < 8; bc++) {
        __syncthreads();
#pragma unroll
        for (int q = 0; q < 16; q++) {
            int f = tid + q * 128;
            ush[f] = g_uT[(n0 * 8 + (f >> 5)) * 256 + (bc << 5) + (f & 31)];
        }
        __syncthreads();
#pragma unroll 4
        for (int bb = 0; bb < 32; bb++) {
            int b = (bc << 5) + bb;
            float uh = 0.f;
#pragma unroll
            for (int j = 0; j < 8; j++)
                uh = fmaf(wr[j], ush[(nl * 8 + j) * 32 + bb], uh);
            acc = fmaf(uh, vsh[i * 257 + b], acc);
        }
    }
    g_blog[(c * 1152 + n) * 16 + i] += acc;
}

__global__ void out_kernel(float* __restrict__ out) {
    int c = blockIdx.x, b = threadIdx.x;
    float s = 0.f;
#pragma unroll
    for (int i = 0; i < 16; i++) {
        float t = g_v[(c * 16 + i) * 256 + b];
        s = fmaf(t, t, s);
    }
    out[b * 10 + c] = s;
}

// ===========================================================================
extern "C" void kernel_launch(void* const* d_in, const int* in_sizes, int n_in,
                              void* d_out, int out_size) {
    const float* x  = (const float*)d_in[0];
    const float* w1 = (const float*)d_in[1];
    const float* b1 = (const float*)d_in[2];
    const float* w2 = (const float*)d_in[3];
    const float* b2 = (const float*)d_in[4];
    const float* W  = (const float*)d_in[5];
    float* out = (float*)d_out;

    const int SMEM_BYTES = 2 * BUFSZ;  // 147456
    cudaFuncSetAttribute(conv2_mma_kernel, cudaFuncAttributeMaxDynamicSharedMemorySize,
                         SMEM_BYTES);

    conv1_kernel<<<dim3(256, 16), 128>>>(x, w1, b1);
    w2prep_kernel<<<(256 * 20736 + 255) / 256, 256>>>(w2);
    conv2_mma_kernel<<<dim3(2, 72), 256, SMEM_BYTES>>>(b2);
    squashT_kernel<<<1152, 256>>>();
    zero_blog_kernel<<<720, 256>>>();

    for (int it = 0; it < 3; it++) {
        softmax_kernel<<<160, 128>>>();
        sgemm_routing_kernel<<<dim3(16, 10), 128>>>(W);
        squashv_kernel<<<160, 256>>>();
        if (it < 2) delta_kernel<<<dim3(144, 10), 128>>>(W);
    }
    out_kernel<<<10, 256>>>(out);
}

// round 8
// speedup vs baseline: 2.2431x; 1.0189x over previous
#include <cuda_runtime.h>
#include <cuda_bf16.h>
#include <math.h>
#include <stdint.h>

// ===========================================================================
// Baseline-PTX helpers (sm_80-level: ldmatrix + mma.sync + cp.async).
// ===========================================================================
__device__ __forceinline__ uint32_t smem_u32(const void* p) {
    uint32_t a;
    asm("{ .reg .u64 t; cvta.to.shared.u64 t, %1; cvt.u32.u64 %0, t; }" : "=r"(a) : "l"(p));
    return a;
}
__device__ __forceinline__ void ldsm_x4(uint32_t r[4], uint32_t addr) {
    asm volatile("ldmatrix.sync.aligned.m8n8.x4.shared.b16 {%0,%1,%2,%3}, [%4];"
                 : "=r"(r[0]), "=r"(r[1]), "=r"(r[2]), "=r"(r[3]) : "r"(addr));
}
__device__ __forceinline__ void mma16816(float c[4], const uint32_t a[4],
                                         uint32_t b0, uint32_t b1) {
    asm volatile(
        "mma.sync.aligned.m16n8k16.row.col.f32.bf16.bf16.f32 "
        "{%0,%1,%2,%3}, {%4,%5,%6,%7}, {%8,%9}, {%0,%1,%2,%3};"
        : "+f"(c[0]), "+f"(c[1]), "+f"(c[2]), "+f"(c[3])
        : "r"(a[0]), "r"(a[1]), "r"(a[2]), "r"(a[3]), "r"(b0), "r"(b1));
}
__device__ __forceinline__ void cp16(uint32_t dst, const void* src) {
    asm volatile("cp.async.cg.shared.global [%0], [%1], 16;" ::"r"(dst), "l"(src));
}
#define CP_COMMIT() asm volatile("cp.async.commit_group;" ::: "memory")
#define CP_WAIT0() asm volatile("cp.async.wait_group 0;" ::: "memory")

// ===========================================================================
// Scratch (device globals)
// ===========================================================================
__device__ float g_h1[256 * 256 * 400];
__device__ float g_uraw[256 * 9216];
__device__ float g_uT[9216 * 256];
__device__ float g_blog[10 * 1152 * 16];
__device__ float g_probs[10 * 1152 * 16];
__device__ float g_spart[10 * 16 * 16 * 256];
__device__ float g_v[10 * 16 * 256];
__device__ __nv_bfloat16 g_w2hi[256 * 20736];
__device__ __nv_bfloat16 g_w2lo[256 * 20736];

// ===========================================================================
// conv1 (unchanged, known-good)
// ===========================================================================
__global__ __launch_bounds__(128) void conv1_kernel(const float* __restrict__ x,
                                                    const float* __restrict__ w,
                                                    const float* __restrict__ bias) {
    int b = blockIdx.x, ocg = blockIdx.y;
    __shared__ float xs[784];
    __shared__ float ws[16 * 81];
    int tid = threadIdx.x;
    for (int i = tid; i < 784; i += 128) xs[i] = x[b * 784 + i];
    for (int i = tid; i < 1296; i += 128) ws[i] = w[ocg * 1296 + i];
    __syncthreads();

    int pr[4], pc[4];
    bool val[4];
#pragma unroll
    for (int q = 0; q < 4; q++) {
        int p = tid + q * 128;
        val[q] = (p < 400);
        int pp = val[q] ? p : 0;
        pr[q] = pp / 20;
        pc[q] = pp % 20;
    }
    float acc[4][16];
#pragma unroll
    for (int q = 0; q < 4; q++)
#pragma unroll
        for (int o = 0; o < 16; o++) acc[q][o] = 0.f;

#pragma unroll 1
    for (int kh = 0; kh < 9; kh++) {
        int rb[4];
#pragma unroll
        for (int q = 0; q < 4; q++) rb[q] = (pr[q] + kh) * 28 + pc[q];
#pragma unroll 1
        for (int kw = 0; kw < 9; kw++) {
            float xv[4];
#pragma unroll
            for (int q = 0; q < 4; q++) xv[q] = xs[rb[q] + kw];
            int ko = kh * 9 + kw;
#pragma unroll
            for (int o = 0; o < 16; o++) {
                float wv = ws[o * 81 + ko];
#pragma unroll
                for (int q = 0; q < 4; q++) acc[q][o] = fmaf(xv[q], wv, acc[q][o]);
            }
        }
    }
#pragma unroll
    for (int o = 0; o < 16; o++) {
        float bv = bias[ocg * 16 + o];
#pragma unroll
        for (int q = 0; q < 4; q++) {
            if (val[q]) {
                float v = acc[q][o] + bv;
                g_h1[(b * 256 + ocg * 16 + o) * 400 + tid + q * 128] = fmaxf(v, 0.f);
            }
        }
    }
}

// ===========================================================================
// w2 fp32 -> bf16 hi/lo split planes
// ===========================================================================
__global__ __launch_bounds__(256) void w2prep_kernel(const float* __restrict__ w2) {
    int i = blockIdx.x * 256 + threadIdx.x;
    if (i < 256 * 20736) {
        float v = w2[i];
        __nv_bfloat16 hi = __float2bfloat16(v);
        __nv_bfloat16 lo = __float2bfloat16(v - __bfloat162float(hi));
        g_w2hi[i] = hi;
        g_w2lo[i] = lo;
    }
}

// ===========================================================================
// conv2 implicit GEMM (mma.sync bf16, 3-term split), BK=64, double-buffered,
// BN=64 for 2 CTAs/SM (4 warps/SMSP -> fill MMA issue bubbles):
// M=256 x N=9216 x K=20736; grid (2,144), 256 thr / 8 warps; warp tile 32x32.
// ===========================================================================
#define ROWB 144
#define PLANE_A (128 * ROWB)              // 18432
#define PLANE_B (64 * ROWB)               // 9216
#define BUFSZ (2 * PLANE_A + 2 * PLANE_B) // 55296 (Ahi|Alo|Bhi|Blo)
#define NSTAGE 324

__global__ __launch_bounds__(256, 2) void conv2_mma_kernel(const float* __restrict__ b2) {
    extern __shared__ __align__(16) unsigned char sm[];
    __shared__ int nAddr[64];

    const int tid = threadIdx.x, lane = tid & 31, wid = tid >> 5;
    const int m0 = blockIdx.x * 128, n0 = blockIdx.y * 64;
    const int wm0 = (wid & 3) * 32;
    const int wn0 = (wid >> 2) * 32;
    const uint32_t sb = smem_u32(sm);

    if (tid < 64) {
        int n = n0 + tid;
        int bb = n / 36, s = n - bb * 36;
        nAddr[tid] = bb * 102400 + (s / 6) * 40 + (s % 6) * 2;
    }
    __syncthreads();

    float acc[2][4][4];
#pragma unroll
    for (int mi = 0; mi < 2; mi++)
#pragma unroll
        for (int nt = 0; nt < 4; nt++)
#pragma unroll
            for (int q = 0; q < 4; q++) acc[mi][nt][q] = 0.f;

    const int kp = tid & 31;   // B k-pair (k = 2kp, 2kp+1) within BK=64
    const int nr = tid >> 5;   // B n start (0..7)
    float bval[16];

    // ---- A: 2 planes x 128 rows x 8x16B chunks -> cp.async ----
    auto issueA = [&](uint32_t base, int kt) {
#pragma unroll
        for (int q = 0; q < 8; q++) {
            int id = q * 256 + tid;   // 2048 chunks: 2 planes x 128 rows x 8
            int plane = id >> 10;
            int rem = id & 1023;
            int row = rem >> 3;
            int c16 = rem & 7;
            const __nv_bfloat16* src = plane ? g_w2lo : g_w2hi;
            cp16(base + plane * PLANE_A + row * ROWB + c16 * 16,
                 &src[(size_t)(m0 + row) * 20736 + kt + c16 * 8]);
        }
        CP_COMMIT();
    };
    // ---- B: gather 16 fp32 values (8 n's x 2 k's) into regs ----
    auto fetchB = [&](int kt) {
        int kg0 = kt + kp * 2;
        int ic0 = kg0 / 81, rr0 = kg0 - ic0 * 81;
        int koff0 = ic0 * 400 + (rr0 / 9) * 20 + (rr0 % 9);
        int kg1 = kg0 + 1;
        int ic1 = kg1 / 81, rr1 = kg1 - ic1 * 81;
        int koff1 = ic1 * 400 + (rr1 / 9) * 20 + (rr1 % 9);
#pragma unroll
        for (int q = 0; q < 8; q++) {
            int base = nAddr[q * 8 + nr];
            bval[2 * q] = g_h1[base + koff0];
            bval[2 * q + 1] = g_h1[base + koff1];
        }
    };
    // ---- B: split + store into buffer (conflict-free) ----
    auto storeB = [&](int buf) {
        unsigned char* bh = sm + buf * BUFSZ + 2 * PLANE_A;
        unsigned char* bl = sm + buf * BUFSZ + 2 * PLANE_A + PLANE_B;
#pragma unroll
        for (int q = 0; q < 8; q++) {
            int n = q * 8 + nr;
            float v0 = bval[2 * q], v1 = bval[2 * q + 1];
            __nv_bfloat16 h0 = __float2bfloat16(v0);
            __nv_bfloat16 h1 = __float2bfloat16(v1);
            __nv_bfloat16 l0 = __float2bfloat16(v0 - __bfloat162float(h0));
            __nv_bfloat16 l1 = __float2bfloat16(v1 - __bfloat162float(h1));
            *(__nv_bfloat162*)(bh + n * ROWB + kp * 4) = __halves2bfloat162(h0, h1);
            *(__nv_bfloat162*)(bl + n * ROWB + kp * 4) = __halves2bfloat162(l0, l1);
        }
    };

    // ---- prologue: stage 0 into buffer 0 ----
    issueA(sb, 0);
    fetchB(0);
    storeB(0);

    for (int s = 0; s < NSTAGE; s++) {
        const int cur = s & 1;
        const uint32_t cb = sb + cur * BUFSZ;
        CP_WAIT0();       // A(cur) arrived
        __syncthreads();  // B(cur) visible; all warps done with buffer cur^1

        if (s + 1 < NSTAGE) {
            issueA(sb + (cur ^ 1) * BUFSZ, (s + 1) * 64);
            fetchB((s + 1) * 64);  // LDGs overlap the MMA block below
        }

        // ---- compute: 4 k-steps x (2m x 4n) x 3 terms = 96 MMAs/warp ----
#pragma unroll
        for (int ks = 0; ks < 4; ks++) {
            uint32_t ah[2][4], al[2][4];
#pragma unroll
            for (int mi = 0; mi < 2; mi++) {
                uint32_t ra = (uint32_t)((wm0 + mi * 16 + (lane & 15)) * ROWB +
                                         ks * 32 + ((lane >> 4) << 4));
                ldsm_x4(ah[mi], cb + ra);
                ldsm_x4(al[mi], cb + PLANE_A + ra);
            }
            uint32_t bh[2][4], bl[2][4];
#pragma unroll
            for (int g = 0; g < 2; g++) {
                uint32_t rb = (uint32_t)((wn0 + g * 16 + (lane & 7) + ((lane >> 4) << 3)) * ROWB +
                                         ks * 32 + (((lane >> 3) & 1) << 4));
                ldsm_x4(bh[g], cb + 2 * PLANE_A + rb);
                ldsm_x4(bl[g], cb + 2 * PLANE_A + PLANE_B + rb);
            }
#pragma unroll
            for (int mi = 0; mi < 2; mi++)
#pragma unroll
                for (int g = 0; g < 2; g++)
#pragma unroll
                    for (int h = 0; h < 2; h++) {
                        int nt = g * 2 + h;
                        mma16816(acc[mi][nt], ah[mi], bh[g][2 * h], bh[g][2 * h + 1]);
                        mma16816(acc[mi][nt], ah[mi], bl[g][2 * h], bl[g][2 * h + 1]);
                        mma16816(acc[mi][nt], al[mi], bh[g][2 * h], bh[g][2 * h + 1]);
                    }
        }

        if (s + 1 < NSTAGE) storeB(cur ^ 1);  // LDG results landed during MMAs
    }

    // ---- epilogue: fragment scatter + bias into u_raw layout ----
#pragma unroll
    for (int mi = 0; mi < 2; mi++) {
        int r0 = m0 + wm0 + mi * 16 + (lane >> 2);
        int r1 = r0 + 8;
        float bias0 = b2[r0], bias1 = b2[r1];
#pragma unroll
        for (int nt = 0; nt < 4; nt++) {
            int c0 = n0 + wn0 + nt * 8 + ((lane & 3) << 1);
            int c1 = c0 + 1;
            int bb0 = c0 / 36, ss0 = c0 - bb0 * 36;
            int bb1 = c1 / 36, ss1 = c1 - bb1 * 36;
            g_uraw[bb0 * 9216 + ss0 + r0 * 36] = acc[mi][nt][0] + bias0;
            g_uraw[bb1 * 9216 + ss1 + r0 * 36] = acc[mi][nt][1] + bias0;
            g_uraw[bb0 * 9216 + ss0 + r1 * 36] = acc[mi][nt][2] + bias1;
            g_uraw[bb1 * 9216 + ss1 + r1 * 36] = acc[mi][nt][3] + bias1;
        }
    }
}

// ===========================================================================
// primary squash + transpose
// ===========================================================================
__global__ __launch_bounds__(256) void squashT_kernel() {
    int idx = blockIdx.x * 256 + threadIdx.x;
    int n = idx >> 8, b = idx & 255;
    const float4* src = (const float4*)&g_uraw[b * 9216 + n * 8];
    float4 u0 = src[0], u1 = src[1];
    float sq = u0.x * u0.x + u0.y * u0.y + u0.z * u0.z + u0.w * u0.w +
               u1.x * u1.x + u1.y * u1.y + u1.z * u1.z + u1.w * u1.w;
    float sc = sq / (1.0f + sq);
    float r[8] = {u0.x * sc, u0.y * sc, u0.z * sc, u0.w * sc,
                  u1.x * sc, u1.y * sc, u1.z * sc, u1.w * sc};
#pragma unroll
    for (int j = 0; j < 8; j++) g_uT[(n * 8 + j) * 256 + b] = r[j];
}

__global__ void zero_blog_kernel() {
    int i = blockIdx.x * 256 + threadIdx.x;
    if (i < 184320) g_blog[i] = 0.f;
}

__global__ __launch_bounds__(128) void softmax_kernel() {
    int c = blockIdx.x >> 4, i = blockIdx.x & 15;
    int tid = threadIdx.x;
    __shared__ float red[128];
    float vals[9];
    float m = -1e30f;
#pragma unroll
    for (int q = 0; q < 9; q++) {
        int n = tid + q * 128;
        vals[q] = g_blog[(c * 1152 + n) * 16 + i];
        m = fmaxf(m, vals[q]);
    }
    red[tid] = m;
    __syncthreads();
    for (int s2 = 64; s2 > 0; s2 >>= 1) {
        if (tid < s2) red[tid] = fmaxf(red[tid], red[tid + s2]);
        __syncthreads();
    }
    float M = red[0];
    __syncthreads();
    float e[9];
    float sum = 0.f;
#pragma unroll
    for (int q = 0; q < 9; q++) {
        e[q] = expf(vals[q] - M);
        sum += e[q];
    }
    red[tid] = sum;
    __syncthreads();
    for (int s2 = 64; s2 > 0; s2 >>= 1) {
        if (tid < s2) red[tid] += red[tid + s2];
        __syncthreads();
    }
    float inv = 1.0f / red[0];
#pragma unroll
    for (int q = 0; q < 9; q++)
        g_probs[(c * 1152 + tid + q * 128) * 16 + i] = e[q] * inv;
}

__global__ __launch_bounds__(128) void sgemm_routing_kernel(const float* __restrict__ W) {
    int nc = blockIdx.x, c = blockIdx.y;
    int tid = threadIdx.x;
    int ig = tid >> 5, bg = tid & 31;
    int i0 = ig << 2;
    __shared__ float uu[2048];
    __shared__ float pw[128];
    int pi = tid >> 3, pj = tid & 7;

    float acc[4][8];
#pragma unroll
    for (int ii = 0; ii < 4; ii++)
#pragma unroll
        for (int bi = 0; bi < 8; bi++) acc[ii][bi] = 0.f;

    for (int n = nc * 72; n < nc * 72 + 72; ++n) {
        __syncthreads();
        const float4* src = (const float4*)&g_uT[n * 2048];
#pragma unroll
        for (int q = 0; q < 4; q++) ((float4*)uu)[tid + q * 128] = src[tid + q * 128];
        pw[tid] = g_probs[(c * 1152 + n) * 16 + pi] *
                  W[((c * 1152 + n) * 16 + pi) * 8 + pj];
        __syncthreads();

        float pwv[4][8];
#pragma unroll
        for (int ii = 0; ii < 4; ii++)
#pragma unroll
            for (int j = 0; j < 8; j++) pwv[ii][j] = pw[(i0 + ii) * 8 + j];

#pragma unroll
        for (int bi = 0; bi < 8; bi++) {
            int b = bg + (bi << 5);
            float uv[8];
#pragma unroll
            for (int j = 0; j < 8; j++) uv[j] = uu[j * 256 + b];
#pragma unroll
            for (int ii = 0; ii < 4; ii++)
#pragma unroll
                for (int j = 0; j < 8; j++)
                    acc[ii][bi] = fmaf(pwv[ii][j], uv[j], acc[ii][bi]);
        }
    }
#pragma unroll
    for (int ii = 0; ii < 4; ii++)
#pragma unroll
        for (int bi = 0; bi < 8; bi++)
            g_spart[((c * 16 + nc) * 16 + i0 + ii) * 256 + bg + (bi << 5)] = acc[ii][bi];
}

__global__ __launch_bounds__(256) void squashv_kernel() {
    int c = blockIdx.x >> 4, i = blockIdx.x & 15;
    int tid = threadIdx.x;
    float sv = 0.f;
#pragma unroll
    for (int ch = 0; ch < 16; ch++)
        sv += g_spart[((c * 16 + ch) * 16 + i) * 256 + tid];
    __shared__ float red[256];
    red[tid] = sv * sv;
    __syncthreads();
    for (int s2 = 128; s2 > 0; s2 >>= 1) {
        if (tid < s2) red[tid] += red[tid + s2];
        __syncthreads();
    }
    float sq = red[0];
    float scale = sq / ((1.0f + sq) * sqrtf(sq));
    g_v[(c * 16 + i) * 256 + tid] = sv * scale;
}

__global__ __launch_bounds__(128) void delta_kernel(const float* __restrict__ W) {
    int n0 = blockIdx.x * 8, c = blockIdx.y;
    int tid = threadIdx.x;
    int nl = tid >> 4, i = tid & 15;
    int n = n0 + nl;
    __shared__ float vsh[16 * 257];
    __shared__ float ush[2048];
    float wr[8];
    const float* wp = &W[((c * 1152 + n) * 16 + i) * 8];
#pragma unroll
    for (int j = 0; j < 8; j++) wr[j] = wp[j];
#pragma unroll
    for (int q = 0; q < 32; q++) {
        int idx = tid + q * 128;
        vsh[(idx >> 8) * 257 + (idx & 255)] = g_v[c * 4096 + idx];
    }
    float acc = 0.f;
    for (int bc = 0; bc < 8; bc++) {
        __syncthreads();
#pragma unroll
        for (int q = 0; q < 16; q++) {
            int f = tid + q * 128;
            ush[f] = g_uT[(n0 * 8 + (f >> 5)) * 256 + (bc << 5) + (f & 31)];
        }
        __syncthreads();
#pragma unroll 4
        for (int bb = 0; bb < 32; bb++) {
            int b = (bc << 5) + bb;
            float uh = 0.f;
#pragma unroll
            for (int j = 0; j < 8; j++)
                uh = fmaf(wr[j], ush[(nl * 8 + j) * 32 + bb], uh);
            acc = fmaf(uh, vsh[i * 257 + b], acc);
        }
    }
    g_blog[(c * 1152 + n) * 16 + i] += acc;
}

__global__ void out_kernel(float* __restrict__ out) {
    int c = blockIdx.x, b = threadIdx.x;
    float s = 0.f;
#pragma unroll
    for (int i = 0; i < 16; i++) {
        float t = g_v[(c * 16 + i) * 256 + b];
        s = fmaf(t, t, s);
    }
    out[b * 10 + c] = s;
}

// ===========================================================================
extern "C" void kernel_launch(void* const* d_in, const int* in_sizes, int n_in,
                              void* d_out, int out_size) {
    const float* x  = (const float*)d_in[0];
    const float* w1 = (const float*)d_in[1];
    const float* b1 = (const float*)d_in[2];
    const float* w2 = (const float*)d_in[3];
    const float* b2 = (const float*)d_in[4];
    const float* W  = (const float*)d_in[5];
    float* out = (float*)d_out;

    const int SMEM_BYTES = 2 * BUFSZ;  // 110592
    cudaFuncSetAttribute(conv2_mma_kernel, cudaFuncAttributeMaxDynamicSharedMemorySize,
                         SMEM_BYTES);

    conv1_kernel<<<dim3(256, 16), 128>>>(x, w1, b1);
    w2prep_kernel<<<(256 * 20736 + 255) / 256, 256>>>(w2);
    conv2_mma_kernel<<<dim3(2, 144), 256, SMEM_BYTES>>>(b2);
    squashT_kernel<<<1152, 256>>>();
    zero_blog_kernel<<<720, 256>>>();

    for (int it = 0; it < 3; it++) {
        softmax_kernel<<<160, 128>>>();
        sgemm_routing_kernel<<<dim3(16, 10), 128>>>(W);
        squashv_kernel<<<160, 256>>>();
        if (it < 2) delta_kernel<<<dim3(144, 10), 128>>>(W);
    }
    out_kernel<<<10, 256>>>(out);
}

// round 9
// speedup vs baseline: 2.4422x; 1.0887x over previous
#include <cuda_runtime.h>
#include <cuda_bf16.h>
#include <math.h>
#include <stdint.h>

// ===========================================================================
// Baseline-PTX helpers (ldmatrix + mma.sync + cp.async). No tcgen05.
// ===========================================================================
__device__ __forceinline__ uint32_t smem_u32(const void* p) {
    uint32_t a;
    asm("{ .reg .u64 t; cvta.to.shared.u64 t, %1; cvt.u32.u64 %0, t; }" : "=r"(a) : "l"(p));
    return a;
}
__device__ __forceinline__ void ldsm_x4(uint32_t r[4], uint32_t addr) {
    asm volatile("ldmatrix.sync.aligned.m8n8.x4.shared.b16 {%0,%1,%2,%3}, [%4];"
                 : "=r"(r[0]), "=r"(r[1]), "=r"(r[2]), "=r"(r[3]) : "r"(addr));
}
// int8 MMA: m16n8k32, s32 accum. K=32 per instruction (2x bf16 k16).
__device__ __forceinline__ void mma_s8(int c[4], const uint32_t a[4],
                                       uint32_t b0, uint32_t b1) {
    asm volatile(
        "mma.sync.aligned.m16n8k32.row.col.s32.s8.s8.s32 "
        "{%0,%1,%2,%3}, {%4,%5,%6,%7}, {%8,%9}, {%0,%1,%2,%3};"
        : "+r"(c[0]), "+r"(c[1]), "+r"(c[2]), "+r"(c[3])
        : "r"(a[0]), "r"(a[1]), "r"(a[2]), "r"(a[3]), "r"(b0), "r"(b1));
}
__device__ __forceinline__ void cp16(uint32_t dst, const void* src) {
    asm volatile("cp.async.cg.shared.global [%0], [%1], 16;" ::"r"(dst), "l"(src));
}
#define CP_COMMIT() asm volatile("cp.async.commit_group;" ::: "memory")
#define CP_WAIT0() asm volatile("cp.async.wait_group 0;" ::: "memory")

// ===========================================================================
// Scratch (device globals)
// ===========================================================================
__device__ float g_h1[256 * 256 * 400];
__device__ float g_uraw[256 * 9216];
__device__ float g_uT[9216 * 256];
__device__ float g_blog[10 * 1152 * 16];
__device__ float g_probs[10 * 1152 * 16];
__device__ float g_spart[10 * 16 * 16 * 256];
__device__ float g_v[10 * 16 * 256];
__device__ char g_w2h8[256 * 20736];   // int8 hi limb of w2 (row-scaled)
__device__ char g_w2l8[256 * 20736];   // int8 lo limb
__device__ float g_dsA[256];           // dequant scale per oc row
__device__ float g_dsB[256];           // dequant scale per batch
__device__ float g_qB[256];            // quant scale per batch (16256/max)

// ===========================================================================
// conv1 (unchanged, known-good)
// ===========================================================================
__global__ __launch_bounds__(128) void conv1_kernel(const float* __restrict__ x,
                                                    const float* __restrict__ w,
                                                    const float* __restrict__ bias) {
    int b = blockIdx.x, ocg = blockIdx.y;
    __shared__ float xs[784];
    __shared__ float ws[16 * 81];
    int tid = threadIdx.x;
    for (int i = tid; i < 784; i += 128) xs[i] = x[b * 784 + i];
    for (int i = tid; i < 1296; i += 128) ws[i] = w[ocg * 1296 + i];
    __syncthreads();

    int pr[4], pc[4];
    bool val[4];
#pragma unroll
    for (int q = 0; q < 4; q++) {
        int p = tid + q * 128;
        val[q] = (p < 400);
        int pp = val[q] ? p : 0;
        pr[q] = pp / 20;
        pc[q] = pp % 20;
    }
    float acc[4][16];
#pragma unroll
    for (int q = 0; q < 4; q++)
#pragma unroll
        for (int o = 0; o < 16; o++) acc[q][o] = 0.f;

#pragma unroll 1
    for (int kh = 0; kh < 9; kh++) {
        int rb[4];
#pragma unroll
        for (int q = 0; q < 4; q++) rb[q] = (pr[q] + kh) * 28 + pc[q];
#pragma unroll 1
        for (int kw = 0; kw < 9; kw++) {
            float xv[4];
#pragma unroll
            for (int q = 0; q < 4; q++) xv[q] = xs[rb[q] + kw];
            int ko = kh * 9 + kw;
#pragma unroll
            for (int o = 0; o < 16; o++) {
                float wv = ws[o * 81 + ko];
#pragma unroll
                for (int q = 0; q < 4; q++) acc[q][o] = fmaf(xv[q], wv, acc[q][o]);
            }
        }
    }
#pragma unroll
    for (int o = 0; o < 16; o++) {
        float bv = bias[ocg * 16 + o];
#pragma unroll
        for (int q = 0; q < 4; q++) {
            if (val[q]) {
                float v = acc[q][o] + bv;
                g_h1[(b * 256 + ocg * 16 + o) * 400 + tid + q * 128] = fmaxf(v, 0.f);
            }
        }
    }
}

// ===========================================================================
// A prep: per-oc-row max of |w2|, then 2-limb int8 quantization (round split)
// ===========================================================================
__global__ __launch_bounds__(256) void aprep_kernel(const float* __restrict__ w2) {
    int m = blockIdx.x, tid = threadIdx.x;
    __shared__ float red[256];
    const float* row = &w2[(size_t)m * 20736];
    float mx = 0.f;
    for (int k = tid; k < 20736; k += 256) mx = fmaxf(mx, fabsf(row[k]));
    red[tid] = mx;
    __syncthreads();
    for (int s = 128; s > 0; s >>= 1) {
        if (tid < s) red[tid] = fmaxf(red[tid], red[tid + s]);
        __syncthreads();
    }
    mx = red[0];
    if (tid == 0) g_dsA[m] = mx * (1.0f / 16256.0f);
    float qa = mx > 0.f ? 16256.0f / mx : 0.f;
    for (int k = tid; k < 20736; k += 256) {
        float a15 = rintf(row[k] * qa);
        float ahf = rintf(a15 * (1.0f / 128.0f));
        int ah = (int)ahf;
        int al = (int)(a15 - 128.0f * ahf);   // in [-64, 64], zero-mean
        g_w2h8[(size_t)m * 20736 + k] = (char)ah;
        g_w2l8[(size_t)m * 20736 + k] = (char)al;
    }
}

// ===========================================================================
// B prep: per-batch max of h1 (h1 >= 0 after relu)
// ===========================================================================
__global__ __launch_bounds__(256) void bprep_kernel() {
    int b = blockIdx.x, tid = threadIdx.x;
    __shared__ float red[256];
    const float* sl = &g_h1[(size_t)b * 102400];
    float mx = 0.f;
    for (int i = tid; i < 102400; i += 256) mx = fmaxf(mx, sl[i]);
    red[tid] = mx;
    __syncthreads();
    for (int s = 128; s > 0; s >>= 1) {
        if (tid < s) red[tid] = fmaxf(red[tid], red[tid + s]);
        __syncthreads();
    }
    if (tid == 0) {
        float m = red[0];
        g_dsB[b] = m * (1.0f / 16256.0f);
        g_qB[b] = m > 0.f ? 16256.0f / m : 0.f;
    }
}

// ===========================================================================
// conv2 implicit GEMM via int8 m16n8k32 (2-limb fixed point, 3 MMAs per k32
// = half the instructions of the bf16 3-term scheme):
// M=256 x N=9216 x K=20736; grid (2,144), 256 thr / 8 warps; warp tile 32x32.
// BK=64, double-buffered; A limbs via cp.async; B gathered fp32 -> quantized.
// D = dsA[m]*dsB[b]*(16384*HH + 128*CROSS) + bias.
// ===========================================================================
#define ROWB 80
#define PLANE_A (128 * ROWB)              // 10240
#define PLANE_B (64 * ROWB)               // 5120
#define BUFSZ (2 * PLANE_A + 2 * PLANE_B) // 30720
#define NSTAGE 324

__global__ __launch_bounds__(256, 2) void conv2_mma_kernel(const float* __restrict__ b2) {
    extern __shared__ __align__(16) unsigned char sm[];
    __shared__ int nAddr[64];
    __shared__ float nQ[64];

    const int tid = threadIdx.x, lane = tid & 31, wid = tid >> 5;
    const int m0 = blockIdx.x * 128, n0 = blockIdx.y * 64;
    const int wm0 = (wid & 3) * 32;
    const int wn0 = (wid >> 2) * 32;
    const uint32_t sb = smem_u32(sm);

    if (tid < 64) {
        int n = n0 + tid;
        int bb = n / 36, s = n - bb * 36;
        nAddr[tid] = bb * 102400 + (s / 6) * 40 + (s % 6) * 2;
        nQ[tid] = g_qB[bb];
    }
    __syncthreads();

    int hh[2][4][4], cr[2][4][4];
#pragma unroll
    for (int mi = 0; mi < 2; mi++)
#pragma unroll
        for (int nt = 0; nt < 4; nt++)
#pragma unroll
            for (int q = 0; q < 4; q++) { hh[mi][nt][q] = 0; cr[mi][nt][q] = 0; }

    const int kc = tid & 15;   // 4-byte k-chunk within BK=64 (16 chunks)
    const int nr = tid >> 4;   // n slot (0..15); n = q*16 + nr
    float bval[16];

    // ---- A: 2 limb planes x 128 rows x 4x16B chunks -> cp.async ----
    auto issueA = [&](uint32_t base, int kt) {
#pragma unroll
        for (int q = 0; q < 4; q++) {
            int id = q * 256 + tid;  // 1024 chunks
            int plane = id >> 9;
            int rem = id & 511;
            int row = rem >> 2;
            int c16 = rem & 3;
            const char* src = plane ? g_w2l8 : g_w2h8;
            cp16(base + plane * PLANE_A + row * ROWB + c16 * 16,
                 src + (size_t)(m0 + row) * 20736 + kt + c16 * 16);
        }
        CP_COMMIT();
    };
    // ---- B: gather 16 fp32 (4 n's x 4 k's) ----
    auto fetchB = [&](int kt) {
        int koff[4];
#pragma unroll
        for (int j = 0; j < 4; j++) {
            int kg = kt + kc * 4 + j;
            int ic = kg / 81, rr = kg - ic * 81;
            koff[j] = ic * 400 + (rr / 9) * 20 + (rr % 9);
        }
#pragma unroll
        for (int q = 0; q < 4; q++) {
            int base = nAddr[q * 16 + nr];
#pragma unroll
            for (int j = 0; j < 4; j++) bval[q * 4 + j] = g_h1[base + koff[j]];
        }
    };
    // ---- B: quantize (round split) + pack + store ----
    auto storeB = [&](int buf) {
        unsigned char* bh = sm + buf * BUFSZ + 2 * PLANE_A;
        unsigned char* bl = bh + PLANE_B;
#pragma unroll
        for (int q = 0; q < 4; q++) {
            int n = q * 16 + nr;
            float qb = nQ[n];
            uint32_t ph = 0, pl = 0;
#pragma unroll
            for (int j = 0; j < 4; j++) {
                float b15 = rintf(bval[q * 4 + j] * qb);
                float bhf = rintf(b15 * (1.0f / 128.0f));
                int bhi = (int)bhf;
                int bli = (int)(b15 - 128.0f * bhf);
                ph |= (uint32_t)(bhi & 0xFF) << (8 * j);
                pl |= (uint32_t)(bli & 0xFF) << (8 * j);
            }
            *(uint32_t*)(bh + n * ROWB + kc * 4) = ph;
            *(uint32_t*)(bl + n * ROWB + kc * 4) = pl;
        }
    };

    issueA(sb, 0);
    fetchB(0);
    storeB(0);

    for (int s = 0; s < NSTAGE; s++) {
        const int cur = s & 1;
        const uint32_t cb = sb + cur * BUFSZ;
        CP_WAIT0();
        __syncthreads();

        if (s + 1 < NSTAGE) {
            issueA(sb + (cur ^ 1) * BUFSZ, (s + 1) * 64);
            fetchB((s + 1) * 64);  // LDGs overlap MMAs below
        }

        // ---- compute: 2 k32-steps x (2m x 4n) x 3 MMAs = 48 MMAs/warp ----
#pragma unroll
        for (int ks = 0; ks < 2; ks++) {
            uint32_t ah[2][4], al[2][4];
#pragma unroll
            for (int mi = 0; mi < 2; mi++) {
                uint32_t ra = (uint32_t)((wm0 + mi * 16 + (lane & 15)) * ROWB +
                                         ks * 32 + ((lane >> 4) << 4));
                ldsm_x4(ah[mi], cb + ra);
                ldsm_x4(al[mi], cb + PLANE_A + ra);
            }
            uint32_t bh[2][4], bl[2][4];
#pragma unroll
            for (int g = 0; g < 2; g++) {
                uint32_t rb = (uint32_t)((wn0 + g * 16 + (lane & 7) + ((lane >> 4) << 3)) * ROWB +
                                         ks * 32 + (((lane >> 3) & 1) << 4));
                ldsm_x4(bh[g], cb + 2 * PLANE_A + rb);
                ldsm_x4(bl[g], cb + 2 * PLANE_A + PLANE_B + rb);
            }
#pragma unroll
            for (int mi = 0; mi < 2; mi++)
#pragma unroll
                for (int g = 0; g < 2; g++)
#pragma unroll
                    for (int h = 0; h < 2; h++) {
                        int nt = g * 2 + h;
                        mma_s8(hh[mi][nt], ah[mi], bh[g][2 * h], bh[g][2 * h + 1]);
                        mma_s8(cr[mi][nt], ah[mi], bl[g][2 * h], bl[g][2 * h + 1]);
                        mma_s8(cr[mi][nt], al[mi], bh[g][2 * h], bh[g][2 * h + 1]);
                    }
        }

        if (s + 1 < NSTAGE) storeB(cur ^ 1);
    }

    // ---- epilogue: dequant + bias, scatter into u_raw layout ----
#pragma unroll
    for (int mi = 0; mi < 2; mi++) {
        int r0 = m0 + wm0 + mi * 16 + (lane >> 2);
        int r1 = r0 + 8;
        float sa0 = g_dsA[r0], sa1 = g_dsA[r1];
        float bias0 = b2[r0], bias1 = b2[r1];
#pragma unroll
        for (int nt = 0; nt < 4; nt++) {
            int c0 = n0 + wn0 + nt * 8 + ((lane & 3) << 1);
            int c1 = c0 + 1;
            int bb0 = c0 / 36, ss0 = c0 - bb0 * 36;
            int bb1 = c1 / 36, ss1 = c1 - bb1 * 36;
            float s0 = g_dsB[bb0], s1 = g_dsB[bb1];
            g_uraw[bb0 * 9216 + ss0 + r0 * 36] =
                sa0 * s0 * (16384.f * (float)hh[mi][nt][0] + 128.f * (float)cr[mi][nt][0]) + bias0;
            g_uraw[bb1 * 9216 + ss1 + r0 * 36] =
                sa0 * s1 * (16384.f * (float)hh[mi][nt][1] + 128.f * (float)cr[mi][nt][1]) + bias0;
            g_uraw[bb0 * 9216 + ss0 + r1 * 36] =
                sa1 * s0 * (16384.f * (float)hh[mi][nt][2] + 128.f * (float)cr[mi][nt][2]) + bias1;
            g_uraw[bb1 * 9216 + ss1 + r1 * 36] =
                sa1 * s1 * (16384.f * (float)hh[mi][nt][3] + 128.f * (float)cr[mi][nt][3]) + bias1;
        }
    }
}

// ===========================================================================
// primary squash + transpose
// ===========================================================================
__global__ __launch_bounds__(256) void squashT_kernel() {
    int idx = blockIdx.x * 256 + threadIdx.x;
    int n = idx >> 8, b = idx & 255;
    const float4* src = (const float4*)&g_uraw[b * 9216 + n * 8];
    float4 u0 = src[0], u1 = src[1];
    float sq = u0.x * u0.x + u0.y * u0.y + u0.z * u0.z + u0.w * u0.w +
               u1.x * u1.x + u1.y * u1.y + u1.z * u1.z + u1.w * u1.w;
    float sc = sq / (1.0f + sq);
    float r[8] = {u0.x * sc, u0.y * sc, u0.z * sc, u0.w * sc,
                  u1.x * sc, u1.y * sc, u1.z * sc, u1.w * sc};
#pragma unroll
    for (int j = 0; j < 8; j++) g_uT[(n * 8 + j) * 256 + b] = r[j];
}

__global__ void zero_blog_kernel() {
    int i = blockIdx.x * 256 + threadIdx.x;
    if (i < 184320) g_blog[i] = 0.f;
}

__global__ __launch_bounds__(128) void softmax_kernel() {
    int c = blockIdx.x >> 4, i = blockIdx.x & 15;
    int tid = threadIdx.x;
    __shared__ float red[128];
    float vals[9];
    float m = -1e30f;
#pragma unroll
    for (int q = 0; q < 9; q++) {
        int n = tid + q * 128;
        vals[q] = g_blog[(c * 1152 + n) * 16 + i];
        m = fmaxf(m, vals[q]);
    }
    red[tid] = m;
    __syncthreads();
    for (int s2 = 64; s2 > 0; s2 >>= 1) {
        if (tid < s2) red[tid] = fmaxf(red[tid], red[tid + s2]);
        __syncthreads();
    }
    float M = red[0];
    __syncthreads();
    float e[9];
    float sum = 0.f;
#pragma unroll
    for (int q = 0; q < 9; q++) {
        e[q] = expf(vals[q] - M);
        sum += e[q];
    }
    red[tid] = sum;
    __syncthreads();
    for (int s2 = 64; s2 > 0; s2 >>= 1) {
        if (tid < s2) red[tid] += red[tid + s2];
        __syncthreads();
    }
    float inv = 1.0f / red[0];
#pragma unroll
    for (int q = 0; q < 9; q++)
        g_probs[(c * 1152 + tid + q * 128) * 16 + i] = e[q] * inv;
}

__global__ __launch_bounds__(128) void sgemm_routing_kernel(const float* __restrict__ W) {
    int nc = blockIdx.x, c = blockIdx.y;
    int tid = threadIdx.x;
    int ig = tid >> 5, bg = tid & 31;
    int i0 = ig << 2;
    __shared__ float uu[2048];
    __shared__ float pw[128];
    int pi = tid >> 3, pj = tid & 7;

    float acc[4][8];
#pragma unroll
    for (int ii = 0; ii < 4; ii++)
#pragma unroll
        for (int bi = 0; bi < 8; bi++) acc[ii][bi] = 0.f;

    for (int n = nc * 72; n < nc * 72 + 72; ++n) {
        __syncthreads();
        const float4* src = (const float4*)&g_uT[n * 2048];
#pragma unroll
        for (int q = 0; q < 4; q++) ((float4*)uu)[tid + q * 128] = src[tid + q * 128];
        pw[tid] = g_probs[(c * 1152 + n) * 16 + pi] *
                  W[((c * 1152 + n) * 16 + pi) * 8 + pj];
        __syncthreads();

        float pwv[4][8];
#pragma unroll
        for (int ii = 0; ii < 4; ii++)
#pragma unroll
            for (int j = 0; j < 8; j++) pwv[ii][j] = pw[(i0 + ii) * 8 + j];

#pragma unroll
        for (int bi = 0; bi < 8; bi++) {
            int b = bg + (bi << 5);
            float uv[8];
#pragma unroll
            for (int j = 0; j < 8; j++) uv[j] = uu[j * 256 + b];
#pragma unroll
            for (int ii = 0; ii < 4; ii++)
#pragma unroll
                for (int j = 0; j < 8; j++)
                    acc[ii][bi] = fmaf(pwv[ii][j], uv[j], acc[ii][bi]);
        }
    }
#pragma unroll
    for (int ii = 0; ii < 4; ii++)
#pragma unroll
        for (int bi = 0; bi < 8; bi++)
            g_spart[((c * 16 + nc) * 16 + i0 + ii) * 256 + bg + (bi << 5)] = acc[ii][bi];
}

__global__ __launch_bounds__(256) void squashv_kernel() {
    int c = blockIdx.x >> 4, i = blockIdx.x & 15;
    int tid = threadIdx.x;
    float sv = 0.f;
#pragma unroll
    for (int ch = 0; ch < 16; ch++)
        sv += g_spart[((c * 16 + ch) * 16 + i) * 256 + tid];
    __shared__ float red[256];
    red[tid] = sv * sv;
    __syncthreads();
    for (int s2 = 128; s2 > 0; s2 >>= 1) {
        if (tid < s2) red[tid] += red[tid + s2];
        __syncthreads();
    }
    float sq = red[0];
    float scale = sq / ((1.0f + sq) * sqrtf(sq));
    g_v[(c * 16 + i) * 256 + tid] = sv * scale;
}

__global__ __launch_bounds__(128) void delta_kernel(const float* __restrict__ W) {
    int n0 = blockIdx.x * 8, c = blockIdx.y;
    int tid = threadIdx.x;
    int nl = tid >> 4, i = tid & 15;
    int n = n0 + nl;
    __shared__ float vsh[16 * 257];
    __shared__ float ush[2048];
    float wr[8];
    const float* wp = &W[((c * 1152 + n) * 16 + i) * 8];
#pragma unroll
    for (int j = 0; j < 8; j++) wr[j] = wp[j];
#pragma unroll
    for (int q = 0; q < 32; q++) {
        int idx = tid + q * 128;
        vsh[(idx >> 8) * 257 + (idx & 255)] = g_v[c * 4096 + idx];
    }
    float acc = 0.f;
    for (int bc = 0; bc < 8; bc++) {
        __syncthreads();
#pragma unroll
        for (int q = 0; q < 16; q++) {
            int f = tid + q * 128;
            ush[f] = g_uT[(n0 * 8 + (f >> 5)) * 256 + (bc << 5) + (f & 31)];
        }
        __syncthreads();
#pragma unroll 4
        for (int bb = 0; bb < 32; bb++) {
            int b = (bc << 5) + bb;
            float uh = 0.f;
#pragma unroll
            for (int j = 0; j < 8; j++)
                uh = fmaf(wr[j], ush[(nl * 8 + j) * 32 + bb], uh);
            acc = fmaf(uh, vsh[i * 257 + b], acc);
        }
    }
    g_blog[(c * 1152 + n) * 16 + i] += acc;
}

__global__ void out_kernel(float* __restrict__ out) {
    int c = blockIdx.x, b = threadIdx.x;
    float s = 0.f;
#pragma unroll
    for (int i = 0; i < 16; i++) {
        float t = g_v[(c * 16 + i) * 256 + b];
        s = fmaf(t, t, s);
    }
    out[b * 10 + c] = s;
}

// ===========================================================================
extern "C" void kernel_launch(void* const* d_in, const int* in_sizes, int n_in,
                              void* d_out, int out_size) {
    const float* x  = (const float*)d_in[0];
    const float* w1 = (const float*)d_in[1];
    const float* b1 = (const float*)d_in[2];
    const float* w2 = (const float*)d_in[3];
    const float* b2 = (const float*)d_in[4];
    const float* W  = (const float*)d_in[5];
    float* out = (float*)d_out;

    const int SMEM_BYTES = 2 * BUFSZ;  // 61440
    cudaFuncSetAttribute(conv2_mma_kernel, cudaFuncAttributeMaxDynamicSharedMemorySize,
                         SMEM_BYTES);

    conv1_kernel<<<dim3(256, 16), 128>>>(x, w1, b1);
    aprep_kernel<<<256, 256>>>(w2);
    bprep_kernel<<<256, 256>>>();
    conv2_mma_kernel<<<dim3(2, 144), 256, SMEM_BYTES>>>(b2);
    squashT_kernel<<<1152, 256>>>();
    zero_blog_kernel<<<720, 256>>>();

    for (int it = 0; it < 3; it++) {
        softmax_kernel<<<160, 128>>>();
        sgemm_routing_kernel<<<dim3(16, 10), 128>>>(W);
        squashv_kernel<<<160, 256>>>();
        if (it < 2) delta_kernel<<<dim3(144, 10), 128>>>(W);
    }
    out_kernel<<<10, 256>>>(out);
}

// round 10
// speedup vs baseline: 2.5387x; 1.0395x over previous
#include <cuda_runtime.h>
#include <math.h>
#include <stdint.h>

// ===========================================================================
// Baseline-PTX helpers (ldmatrix + mma.sync + cp.async). No tcgen05.
// ===========================================================================
__device__ __forceinline__ uint32_t smem_u32(const void* p) {
    uint32_t a;
    asm("{ .reg .u64 t; cvta.to.shared.u64 t, %1; cvt.u32.u64 %0, t; }" : "=r"(a) : "l"(p));
    return a;
}
__device__ __forceinline__ void ldsm_x4(uint32_t r[4], uint32_t addr) {
    asm volatile("ldmatrix.sync.aligned.m8n8.x4.shared.b16 {%0,%1,%2,%3}, [%4];"
                 : "=r"(r[0]), "=r"(r[1]), "=r"(r[2]), "=r"(r[3]) : "r"(addr));
}
__device__ __forceinline__ void mma_s8(int c[4], const uint32_t a[4],
                                       uint32_t b0, uint32_t b1) {
    asm volatile(
        "mma.sync.aligned.m16n8k32.row.col.s32.s8.s8.s32 "
        "{%0,%1,%2,%3}, {%4,%5,%6,%7}, {%8,%9}, {%0,%1,%2,%3};"
        : "+r"(c[0]), "+r"(c[1]), "+r"(c[2]), "+r"(c[3])
        : "r"(a[0]), "r"(a[1]), "r"(a[2]), "r"(a[3]), "r"(b0), "r"(b1));
}
__device__ __forceinline__ void cp16(uint32_t dst, const void* src) {
    asm volatile("cp.async.cg.shared.global [%0], [%1], 16;" ::"r"(dst), "l"(src));
}
#define CP_COMMIT() asm volatile("cp.async.commit_group;" ::: "memory")
#define CP_WAIT1() asm volatile("cp.async.wait_group 1;" ::: "memory")

// ===========================================================================
// Scratch (device globals)
// ===========================================================================
__device__ float g_h1[256 * 256 * 400];
__device__ float g_uraw[256 * 9216];
__device__ float g_uT[9216 * 256];
__device__ float g_blog[10 * 1152 * 16];
__device__ float g_probs[10 * 1152 * 16];
__device__ float g_spart[10 * 16 * 16 * 256];
__device__ float g_v[10 * 16 * 256];
__device__ char g_w2h8[256 * 20736];    // int8 hi limb of w2 (row-scaled)
__device__ char g_w2l8[256 * 20736];    // int8 lo limb
__device__ char g_bqh[9216 * 20736];    // im2col B, hi limb (per-batch scaled)
__device__ char g_bql[9216 * 20736];    // im2col B, lo limb
__device__ float g_dsA[256];            // dequant scale per oc row
__device__ float g_dsB[256];            // dequant scale per batch
__device__ float g_qB[256];             // quant scale per batch (16256/max)

// ===========================================================================
// conv1 (unchanged, known-good)
// ===========================================================================
__global__ __launch_bounds__(128) void conv1_kernel(const float* __restrict__ x,
                                                    const float* __restrict__ w,
                                                    const float* __restrict__ bias) {
    int b = blockIdx.x, ocg = blockIdx.y;
    __shared__ float xs[784];
    __shared__ float ws[16 * 81];
    int tid = threadIdx.x;
    for (int i = tid; i < 784; i += 128) xs[i] = x[b * 784 + i];
    for (int i = tid; i < 1296; i += 128) ws[i] = w[ocg * 1296 + i];
    __syncthreads();

    int pr[4], pc[4];
    bool val[4];
#pragma unroll
    for (int q = 0; q < 4; q++) {
        int p = tid + q * 128;
        val[q] = (p < 400);
        int pp = val[q] ? p : 0;
        pr[q] = pp / 20;
        pc[q] = pp % 20;
    }
    float acc[4][16];
#pragma unroll
    for (int q = 0; q < 4; q++)
#pragma unroll
        for (int o = 0; o < 16; o++) acc[q][o] = 0.f;

#pragma unroll 1
    for (int kh = 0; kh < 9; kh++) {
        int rb[4];
#pragma unroll
        for (int q = 0; q < 4; q++) rb[q] = (pr[q] + kh) * 28 + pc[q];
#pragma unroll 1
        for (int kw = 0; kw < 9; kw++) {
            float xv[4];
#pragma unroll
            for (int q = 0; q < 4; q++) xv[q] = xs[rb[q] + kw];
            int ko = kh * 9 + kw;
#pragma unroll
            for (int o = 0; o < 16; o++) {
                float wv = ws[o * 81 + ko];
#pragma unroll
                for (int q = 0; q < 4; q++) acc[q][o] = fmaf(xv[q], wv, acc[q][o]);
            }
        }
    }
#pragma unroll
    for (int o = 0; o < 16; o++) {
        float bv = bias[ocg * 16 + o];
#pragma unroll
        for (int q = 0; q < 4; q++) {
            if (val[q]) {
                float v = acc[q][o] + bv;
                g_h1[(b * 256 + ocg * 16 + o) * 400 + tid + q * 128] = fmaxf(v, 0.f);
            }
        }
    }
}

// ===========================================================================
// A prep: per-oc-row max of |w2|, 2-limb int8 quantization (round split)
// ===========================================================================
__global__ __launch_bounds__(256) void aprep_kernel(const float* __restrict__ w2) {
    int m = blockIdx.x, tid = threadIdx.x;
    __shared__ float red[256];
    const float* row = &w2[(size_t)m * 20736];
    float mx = 0.f;
    for (int k = tid; k < 20736; k += 256) mx = fmaxf(mx, fabsf(row[k]));
    red[tid] = mx;
    __syncthreads();
    for (int s = 128; s > 0; s >>= 1) {
        if (tid < s) red[tid] = fmaxf(red[tid], red[tid + s]);
        __syncthreads();
    }
    mx = red[0];
    if (tid == 0) g_dsA[m] = mx * (1.0f / 16256.0f);
    float qa = mx > 0.f ? 16256.0f / mx : 0.f;
    for (int k = tid; k < 20736; k += 256) {
        float a15 = rintf(row[k] * qa);
        float ahf = rintf(a15 * (1.0f / 128.0f));
        int ah = (int)ahf;
        int al = (int)(a15 - 128.0f * ahf);
        g_w2h8[(size_t)m * 20736 + k] = (char)ah;
        g_w2l8[(size_t)m * 20736 + k] = (char)al;
    }
}

// ===========================================================================
// B prep: per-batch max of h1 (h1 >= 0 after relu)
// ===========================================================================
__global__ __launch_bounds__(256) void bprep_kernel() {
    int b = blockIdx.x, tid = threadIdx.x;
    __shared__ float red[256];
    const float* sl = &g_h1[(size_t)b * 102400];
    float mx = 0.f;
    for (int i = tid; i < 102400; i += 256) mx = fmaxf(mx, sl[i]);
    red[tid] = mx;
    __syncthreads();
    for (int s = 128; s > 0; s >>= 1) {
        if (tid < s) red[tid] = fmaxf(red[tid], red[tid + s]);
        __syncthreads();
    }
    if (tid == 0) {
        float m = red[0];
        g_dsB[b] = m * (1.0f / 16256.0f);
        g_qB[b] = m > 0.f ? 16256.0f / m : 0.f;
    }
}

// ===========================================================================
// bquant: materialize im2col B as two int8 limb planes [n=9216][k=20736].
// One block per n row; quantization math identical to R9 -> same numerics.
// ===========================================================================
__global__ __launch_bounds__(256) void bquant_kernel() {
    int n = blockIdx.x;
    int bb = n / 36, s = n - bb * 36;
    int base = bb * 102400 + (s / 6) * 40 + (s % 6) * 2;
    float qb = g_qB[bb];
    size_t rowo = (size_t)n * 20736;
    for (int k0 = threadIdx.x * 4; k0 < 20736; k0 += 1024) {
        uint32_t ph = 0, pl = 0;
#pragma unroll
        for (int j = 0; j < 4; j++) {
            int kg = k0 + j;
            int ic = kg / 81, rr = kg - ic * 81;
            float v = g_h1[base + ic * 400 + (rr / 9) * 20 + (rr % 9)];
            float b15 = rintf(v * qb);
            float bhf = rintf(b15 * (1.0f / 128.0f));
            int bhi = (int)bhf;
            int bli = (int)(b15 - 128.0f * bhf);
            ph |= (uint32_t)(bhi & 0xFF) << (8 * j);
            pl |= (uint32_t)(bli & 0xFF) << (8 * j);
        }
        *(uint32_t*)(g_bqh + rowo + k0) = ph;
        *(uint32_t*)(g_bql + rowo + k0) = pl;
    }
}

// ===========================================================================
// conv2: pure int8 GEMM (2-limb, 3 MMAs per k32). Both operands cp.async.
// M=256 x N=9216 x K=20736; grid (2,144), 256 thr / 8 warps; warp tile 32x32.
// BK=64, 3-stage cp.async ring (loads 2 stages ahead, zero LDG exposure).
// D = dsA[m]*dsB[b]*(16384*HH + 128*CROSS) + bias.
// ===========================================================================
#define ROWB 80
#define PLANE_A (128 * ROWB)               // 10240
#define PLANE_B (64 * ROWB)                // 5120
#define STG (2 * PLANE_A + 2 * PLANE_B)    // 30720 per stage (Ah|Al|Bh|Bl)
#define NSTAGE 324

__global__ __launch_bounds__(256, 2) void conv2_mma_kernel(const float* __restrict__ b2) {
    extern __shared__ __align__(16) unsigned char sm[];

    const int tid = threadIdx.x, lane = tid & 31, wid = tid >> 5;
    const int m0 = blockIdx.x * 128, n0 = blockIdx.y * 64;
    const int wm0 = (wid & 3) * 32;
    const int wn0 = (wid >> 2) * 32;
    const uint32_t sb = smem_u32(sm);

    int hh[2][4][4], cr[2][4][4];
#pragma unroll
    for (int mi = 0; mi < 2; mi++)
#pragma unroll
        for (int nt = 0; nt < 4; nt++)
#pragma unroll
            for (int q = 0; q < 4; q++) { hh[mi][nt][q] = 0; cr[mi][nt][q] = 0; }

    // ---- stage loader: A limbs (1024 chunks) + B limbs (512 chunks) ----
    auto issue = [&](uint32_t base, int kt) {
#pragma unroll
        for (int q = 0; q < 4; q++) {
            int id = q * 256 + tid;
            int plane = id >> 9;
            int rem = id & 511;
            int row = rem >> 2;
            int c16 = rem & 3;
            const char* src = plane ? g_w2l8 : g_w2h8;
            cp16(base + plane * PLANE_A + row * ROWB + c16 * 16,
                 src + (size_t)(m0 + row) * 20736 + kt + c16 * 16);
        }
#pragma unroll
        for (int q = 0; q < 2; q++) {
            int id = q * 256 + tid;
            int plane = id >> 8;
            int rem = id & 255;
            int row = rem >> 2;
            int c16 = rem & 3;
            const char* src = plane ? g_bql : g_bqh;
            cp16(base + 2 * PLANE_A + plane * PLANE_B + row * ROWB + c16 * 16,
                 src + (size_t)(n0 + row) * 20736 + kt + c16 * 16);
        }
        CP_COMMIT();
    };

    // ---- prologue: stages 0,1 in flight ----
    issue(sb, 0);
    issue(sb + STG, 64);

    for (int s = 0; s < NSTAGE; s++) {
        const uint32_t cb = sb + (uint32_t)(s % 3) * STG;
        CP_WAIT1();       // stage s landed (s+1 may still be in flight)
        __syncthreads();  // all warps done computing stage s-1 (buffer (s+2)%3)
        if (s + 2 < NSTAGE) issue(sb + (uint32_t)((s + 2) % 3) * STG, (s + 2) * 64);

        // ---- compute: 2 k32-steps x (2m x 4n) x 3 MMAs = 48 MMAs/warp ----
#pragma unroll
        for (int ks = 0; ks < 2; ks++) {
            uint32_t ah[2][4], al[2][4];
#pragma unroll
            for (int mi = 0; mi < 2; mi++) {
                uint32_t ra = (uint32_t)((wm0 + mi * 16 + (lane & 15)) * ROWB +
                                         ks * 32 + ((lane >> 4) << 4));
                ldsm_x4(ah[mi], cb + ra);
                ldsm_x4(al[mi], cb + PLANE_A + ra);
            }
            uint32_t bh[2][4], bl[2][4];
#pragma unroll
            for (int g = 0; g < 2; g++) {
                uint32_t rb = (uint32_t)((wn0 + g * 16 + (lane & 7) + ((lane >> 4) << 3)) * ROWB +
                                         ks * 32 + (((lane >> 3) & 1) << 4));
                ldsm_x4(bh[g], cb + 2 * PLANE_A + rb);
                ldsm_x4(bl[g], cb + 2 * PLANE_A + PLANE_B + rb);
            }
#pragma unroll
            for (int mi = 0; mi < 2; mi++)
#pragma unroll
                for (int g = 0; g < 2; g++)
#pragma unroll
                    for (int h = 0; h < 2; h++) {
                        int nt = g * 2 + h;
                        mma_s8(hh[mi][nt], ah[mi], bh[g][2 * h], bh[g][2 * h + 1]);
                        mma_s8(cr[mi][nt], ah[mi], bl[g][2 * h], bl[g][2 * h + 1]);
                        mma_s8(cr[mi][nt], al[mi], bh[g][2 * h], bh[g][2 * h + 1]);
                    }
        }
    }

    // ---- epilogue: dequant + bias, scatter into u_raw layout ----
#pragma unroll
    for (int mi = 0; mi < 2; mi++) {
        int r0 = m0 + wm0 + mi * 16 + (lane >> 2);
        int r1 = r0 + 8;
        float sa0 = g_dsA[r0], sa1 = g_dsA[r1];
        float bias0 = b2[r0], bias1 = b2[r1];
#pragma unroll
        for (int nt = 0; nt < 4; nt++) {
            int c0 = n0 + wn0 + nt * 8 + ((lane & 3) << 1);
            int c1 = c0 + 1;
            int bb0 = c0 / 36, ss0 = c0 - bb0 * 36;
            int bb1 = c1 / 36, ss1 = c1 - bb1 * 36;
            float s0 = g_dsB[bb0], s1 = g_dsB[bb1];
            g_uraw[bb0 * 9216 + ss0 + r0 * 36] =
                sa0 * s0 * (16384.f * (float)hh[mi][nt][0] + 128.f * (float)cr[mi][nt][0]) + bias0;
            g_uraw[bb1 * 9216 + ss1 + r0 * 36] =
                sa0 * s1 * (16384.f * (float)hh[mi][nt][1] + 128.f * (float)cr[mi][nt][1]) + bias0;
            g_uraw[bb0 * 9216 + ss0 + r1 * 36] =
                sa1 * s0 * (16384.f * (float)hh[mi][nt][2] + 128.f * (float)cr[mi][nt][2]) + bias1;
            g_uraw[bb1 * 9216 + ss1 + r1 * 36] =
                sa1 * s1 * (16384.f * (float)hh[mi][nt][3] + 128.f * (float)cr[mi][nt][3]) + bias1;
        }
    }
}

// ===========================================================================
// primary squash + transpose
// ===========================================================================
__global__ __launch_bounds__(256) void squashT_kernel() {
    int idx = blockIdx.x * 256 + threadIdx.x;
    int n = idx >> 8, b = idx & 255;
    const float4* src = (const float4*)&g_uraw[b * 9216 + n * 8];
    float4 u0 = src[0], u1 = src[1];
    float sq = u0.x * u0.x + u0.y * u0.y + u0.z * u0.z + u0.w * u0.w +
               u1.x * u1.x + u1.y * u1.y + u1.z * u1.z + u1.w * u1.w;
    float sc = sq / (1.0f + sq);
    float r[8] = {u0.x * sc, u0.y * sc, u0.z * sc, u0.w * sc,
                  u1.x * sc, u1.y * sc, u1.z * sc, u1.w * sc};
#pragma unroll
    for (int j = 0; j < 8; j++) g_uT[(n * 8 + j) * 256 + b] = r[j];
}

__global__ void zero_blog_kernel() {
    int i = blockIdx.x * 256 + threadIdx.x;
    if (i < 184320) g_blog[i] = 0.f;
}

__global__ __launch_bounds__(128) void softmax_kernel() {
    int c = blockIdx.x >> 4, i = blockIdx.x & 15;
    int tid = threadIdx.x;
    __shared__ float red[128];
    float vals[9];
    float m = -1e30f;
#pragma unroll
    for (int q = 0; q < 9; q++) {
        int n = tid + q * 128;
        vals[q] = g_blog[(c * 1152 + n) * 16 + i];
        m = fmaxf(m, vals[q]);
    }
    red[tid] = m;
    __syncthreads();
    for (int s2 = 64; s2 > 0; s2 >>= 1) {
        if (tid < s2) red[tid] = fmaxf(red[tid], red[tid + s2]);
        __syncthreads();
    }
    float M = red[0];
    __syncthreads();
    float e[9];
    float sum = 0.f;
#pragma unroll
    for (int q = 0; q < 9; q++) {
        e[q] = expf(vals[q] - M);
        sum += e[q];
    }
    red[tid] = sum;
    __syncthreads();
    for (int s2 = 64; s2 > 0; s2 >>= 1) {
        if (tid < s2) red[tid] += red[tid + s2];
        __syncthreads();
    }
    float inv = 1.0f / red[0];
#pragma unroll
    for (int q = 0; q < 9; q++)
        g_probs[(c * 1152 + tid + q * 128) * 16 + i] = e[q] * inv;
}

__global__ __launch_bounds__(128) void sgemm_routing_kernel(const float* __restrict__ W) {
    int nc = blockIdx.x, c = blockIdx.y;
    int tid = threadIdx.x;
    int ig = tid >> 5, bg = tid & 31;
    int i0 = ig << 2;
    __shared__ float uu[2048];
    __shared__ float pw[128];
    int pi = tid >> 3, pj = tid & 7;

    float acc[4][8];
#pragma unroll
    for (int ii = 0; ii < 4; ii++)
#pragma unroll
        for (int bi = 0; bi < 8; bi++) acc[ii][bi] = 0.f;

    for (int n = nc * 72; n < nc * 72 + 72; ++n) {
        __syncthreads();
        const float4* src = (const float4*)&g_uT[n * 2048];
#pragma unroll
        for (int q = 0; q < 4; q++) ((float4*)uu)[tid + q * 128] = src[tid + q * 128];
        pw[tid] = g_probs[(c * 1152 + n) * 16 + pi] *
                  W[((c * 1152 + n) * 16 + pi) * 8 + pj];
        __syncthreads();

        float pwv[4][8];
#pragma unroll
        for (int ii = 0; ii < 4; ii++)
#pragma unroll
            for (int j = 0; j < 8; j++) pwv[ii][j] = pw[(i0 + ii) * 8 + j];

#pragma unroll
        for (int bi = 0; bi < 8; bi++) {
            int b = bg + (bi << 5);
            float uv[8];
#pragma unroll
            for (int j = 0; j < 8; j++) uv[j] = uu[j * 256 + b];
#pragma unroll
            for (int ii = 0; ii < 4; ii++)
#pragma unroll
                for (int j = 0; j < 8; j++)
                    acc[ii][bi] = fmaf(pwv[ii][j], uv[j], acc[ii][bi]);
        }
    }
#pragma unroll
    for (int ii = 0; ii < 4; ii++)
#pragma unroll
        for (int bi = 0; bi < 8; bi++)
            g_spart[((c * 16 + nc) * 16 + i0 + ii) * 256 + bg + (bi << 5)] = acc[ii][bi];
}

__global__ __launch_bounds__(256) void squashv_kernel() {
    int c = blockIdx.x >> 4, i = blockIdx.x & 15;
    int tid = threadIdx.x;
    float sv = 0.f;
#pragma unroll
    for (int ch = 0; ch < 16; ch++)
        sv += g_spart[((c * 16 + ch) * 16 + i) * 256 + tid];
    __shared__ float red[256];
    red[tid] = sv * sv;
    __syncthreads();
    for (int s2 = 128; s2 > 0; s2 >>= 1) {
        if (tid < s2) red[tid] += red[tid + s2];
        __syncthreads();
    }
    float sq = red[0];
    float scale = sq / ((1.0f + sq) * sqrtf(sq));
    g_v[(c * 16 + i) * 256 + tid] = sv * scale;
}

__global__ __launch_bounds__(128) void delta_kernel(const float* __restrict__ W) {
    int n0 = blockIdx.x * 8, c = blockIdx.y;
    int tid = threadIdx.x;
    int nl = tid >> 4, i = tid & 15;
    int n = n0 + nl;
    __shared__ float vsh[16 * 257];
    __shared__ float ush[2048];
    float wr[8];
    const float* wp = &W[((c * 1152 + n) * 16 + i) * 8];
#pragma unroll
    for (int j = 0; j < 8; j++) wr[j] = wp[j];
#pragma unroll
    for (int q = 0; q < 32; q++) {
        int idx = tid + q * 128;
        vsh[(idx >> 8) * 257 + (idx & 255)] = g_v[c * 4096 + idx];
    }
    float acc = 0.f;
    for (int bc = 0; bc < 8; bc++) {
        __syncthreads();
#pragma unroll
        for (int q = 0; q < 16; q++) {
            int f = tid + q * 128;
            ush[f] = g_uT[(n0 * 8 + (f >> 5)) * 256 + (bc << 5) + (f & 31)];
        }
        __syncthreads();
#pragma unroll 4
        for (int bb = 0; bb < 32; bb++) {
            int b = (bc << 5) + bb;
            float uh = 0.f;
#pragma unroll
            for (int j = 0; j < 8; j++)
                uh = fmaf(wr[j], ush[(nl * 8 + j) * 32 + bb], uh);
            acc = fmaf(uh, vsh[i * 257 + b], acc);
        }
    }
    g_blog[(c * 1152 + n) * 16 + i] += acc;
}

__global__ void out_kernel(float* __restrict__ out) {
    int c = blockIdx.x, b = threadIdx.x;
    float s = 0.f;
#pragma unroll
    for (int i = 0; i < 16; i++) {
        float t = g_v[(c * 16 + i) * 256 + b];
        s = fmaf(t, t, s);
    }
    out[b * 10 + c] = s;
}

// ===========================================================================
extern "C" void kernel_launch(void* const* d_in, const int* in_sizes, int n_in,
                              void* d_out, int out_size) {
    const float* x  = (const float*)d_in[0];
    const float* w1 = (const float*)d_in[1];
    const float* b1 = (const float*)d_in[2];
    const float* w2 = (const float*)d_in[3];
    const float* b2 = (const float*)d_in[4];
    const float* W  = (const float*)d_in[5];
    float* out = (float*)d_out;

    const int SMEM_BYTES = 3 * STG;  // 92160
    cudaFuncSetAttribute(conv2_mma_kernel, cudaFuncAttributeMaxDynamicSharedMemorySize,
                         SMEM_BYTES);

    conv1_kernel<<<dim3(256, 16), 128>>>(x, w1, b1);
    aprep_kernel<<<256, 256>>>(w2);
    bprep_kernel<<<256, 256>>>();
    bquant_kernel<<<9216, 256>>>();
    conv2_mma_kernel<<<dim3(2, 144), 256, SMEM_BYTES>>>(b2);
    squashT_kernel<<<1152, 256>>>();
    zero_blog_kernel<<<720, 256>>>();

    for (int it = 0; it < 3; it++) {
        softmax_kernel<<<160, 128>>>();
        sgemm_routing_kernel<<<dim3(16, 10), 128>>>(W);
        squashv_kernel<<<160, 256>>>();
        if (it < 2) delta_kernel<<<dim3(144, 10), 128>>>(W);
    }
    out_kernel<<<10, 256>>>(out);
}

// round 11
// speedup vs baseline: 2.7756x; 1.0933x over previous
#include <cuda_runtime.h>
#include <math.h>
#include <stdint.h>

// ===========================================================================
// Baseline-PTX helpers (ldmatrix + mma.sync + cp.async). No tcgen05.
// ===========================================================================
__device__ __forceinline__ uint32_t smem_u32(const void* p) {
    uint32_t a;
    asm("{ .reg .u64 t; cvta.to.shared.u64 t, %1; cvt.u32.u64 %0, t; }" : "=r"(a) : "l"(p));
    return a;
}
__device__ __forceinline__ void ldsm_x4(uint32_t r[4], uint32_t addr) {
    asm volatile("ldmatrix.sync.aligned.m8n8.x4.shared.b16 {%0,%1,%2,%3}, [%4];"
                 : "=r"(r[0]), "=r"(r[1]), "=r"(r[2]), "=r"(r[3]) : "r"(addr));
}
__device__ __forceinline__ void mma_s8(int c[4], const uint32_t a[4],
                                       uint32_t b0, uint32_t b1) {
    asm volatile(
        "mma.sync.aligned.m16n8k32.row.col.s32.s8.s8.s32 "
        "{%0,%1,%2,%3}, {%4,%5,%6,%7}, {%8,%9}, {%0,%1,%2,%3};"
        : "+r"(c[0]), "+r"(c[1]), "+r"(c[2]), "+r"(c[3])
        : "r"(a[0]), "r"(a[1]), "r"(a[2]), "r"(a[3]), "r"(b0), "r"(b1));
}
__device__ __forceinline__ void cp16(uint32_t dst, const void* src) {
    asm volatile("cp.async.cg.shared.global [%0], [%1], 16;" ::"r"(dst), "l"(src));
}
#define CP_COMMIT() asm volatile("cp.async.commit_group;" ::: "memory")
#define CP_WAIT1() asm volatile("cp.async.wait_group 1;" ::: "memory")

// ===========================================================================
// Scratch (device globals)
// ===========================================================================
__device__ float g_h1[256 * 256 * 400];
__device__ float g_uraw[256 * 9216];
__device__ float g_uT[9216 * 256];
__device__ float g_blog[10 * 1152 * 16];
__device__ float g_probs[10 * 1152 * 16];
__device__ float g_spart[10 * 32 * 16 * 256];
__device__ float g_v[10 * 16 * 256];
__device__ char g_w2h8[256 * 20736];    // int8 hi limb of w2 (row-scaled)
__device__ char g_w2l8[256 * 20736];    // int8 lo limb
__device__ char g_bqh[9216 * 20736];    // im2col B, hi limb (per-batch scaled)
__device__ char g_bql[9216 * 20736];    // im2col B, lo limb
__device__ float g_dsA[256];            // dequant scale per oc row
__device__ float g_dsB[256];            // dequant scale per batch
__device__ float g_qB[256];             // quant scale per batch (16256/max)

// ===========================================================================
// conv1 (unchanged, known-good)
// ===========================================================================
__global__ __launch_bounds__(128) void conv1_kernel(const float* __restrict__ x,
                                                    const float* __restrict__ w,
                                                    const float* __restrict__ bias) {
    int b = blockIdx.x, ocg = blockIdx.y;
    __shared__ float xs[784];
    __shared__ float ws[16 * 81];
    int tid = threadIdx.x;
    for (int i = tid; i < 784; i += 128) xs[i] = x[b * 784 + i];
    for (int i = tid; i < 1296; i += 128) ws[i] = w[ocg * 1296 + i];
    __syncthreads();

    int pr[4], pc[4];
    bool val[4];
#pragma unroll
    for (int q = 0; q < 4; q++) {
        int p = tid + q * 128;
        val[q] = (p < 400);
        int pp = val[q] ? p : 0;
        pr[q] = pp / 20;
        pc[q] = pp % 20;
    }
    float acc[4][16];
#pragma unroll
    for (int q = 0; q < 4; q++)
#pragma unroll
        for (int o = 0; o < 16; o++) acc[q][o] = 0.f;

#pragma unroll 1
    for (int kh = 0; kh < 9; kh++) {
        int rb[4];
#pragma unroll
        for (int q = 0; q < 4; q++) rb[q] = (pr[q] + kh) * 28 + pc[q];
#pragma unroll 1
        for (int kw = 0; kw < 9; kw++) {
            float xv[4];
#pragma unroll
            for (int q = 0; q < 4; q++) xv[q] = xs[rb[q] + kw];
            int ko = kh * 9 + kw;
#pragma unroll
            for (int o = 0; o < 16; o++) {
                float wv = ws[o * 81 + ko];
#pragma unroll
                for (int q = 0; q < 4; q++) acc[q][o] = fmaf(xv[q], wv, acc[q][o]);
            }
        }
    }
#pragma unroll
    for (int o = 0; o < 16; o++) {
        float bv = bias[ocg * 16 + o];
#pragma unroll
        for (int q = 0; q < 4; q++) {
            if (val[q]) {
                float v = acc[q][o] + bv;
                g_h1[(b * 256 + ocg * 16 + o) * 400 + tid + q * 128] = fmaxf(v, 0.f);
            }
        }
    }
}

// ===========================================================================
// A prep: per-oc-row max of |w2|, 2-limb int8 quantization (round split)
// ===========================================================================
__global__ __launch_bounds__(256) void aprep_kernel(const float* __restrict__ w2) {
    int m = blockIdx.x, tid = threadIdx.x;
    __shared__ float red[256];
    const float* row = &w2[(size_t)m * 20736];
    float mx = 0.f;
    for (int k = tid; k < 20736; k += 256) mx = fmaxf(mx, fabsf(row[k]));
    red[tid] = mx;
    __syncthreads();
    for (int s = 128; s > 0; s >>= 1) {
        if (tid < s) red[tid] = fmaxf(red[tid], red[tid + s]);
        __syncthreads();
    }
    mx = red[0];
    if (tid == 0) g_dsA[m] = mx * (1.0f / 16256.0f);
    float qa = mx > 0.f ? 16256.0f / mx : 0.f;
    for (int k = tid; k < 20736; k += 256) {
        float a15 = rintf(row[k] * qa);
        float ahf = rintf(a15 * (1.0f / 128.0f));
        int ah = (int)ahf;
        int al = (int)(a15 - 128.0f * ahf);
        g_w2h8[(size_t)m * 20736 + k] = (char)ah;
        g_w2l8[(size_t)m * 20736 + k] = (char)al;
    }
}

// ===========================================================================
// B prep: per-batch max of h1 (h1 >= 0 after relu)
// ===========================================================================
__global__ __launch_bounds__(256) void bprep_kernel() {
    int b = blockIdx.x, tid = threadIdx.x;
    __shared__ float red[256];
    const float* sl = &g_h1[(size_t)b * 102400];
    float mx = 0.f;
    for (int i = tid; i < 102400; i += 256) mx = fmaxf(mx, sl[i]);
    red[tid] = mx;
    __syncthreads();
    for (int s = 128; s > 0; s >>= 1) {
        if (tid < s) red[tid] = fmaxf(red[tid], red[tid + s]);
        __syncthreads();
    }
    if (tid == 0) {
        float m = red[0];
        g_dsB[b] = m * (1.0f / 16256.0f);
        g_qB[b] = m > 0.f ? 16256.0f / m : 0.f;
    }
}

// ===========================================================================
// bquant: im2col B -> two int8 limb planes. Integer fast path (h1 >= 0):
// s16 = rn(v*qb); hi = (s16+64)>>7; lo = s16 - 128*hi; pack via byte_perm.
// ===========================================================================
__global__ __launch_bounds__(256) void bquant_kernel() {
    int n = blockIdx.x;
    int bb = n / 36, s = n - bb * 36;
    int base = bb * 102400 + (s / 6) * 40 + (s % 6) * 2;
    float qb = g_qB[bb];
    size_t rowo = (size_t)n * 20736;
    for (int k0 = threadIdx.x * 4; k0 < 20736; k0 += 1024) {
        int hi[4], lo[4];
#pragma unroll
        for (int j = 0; j < 4; j++) {
            int kg = k0 + j;
            int ic = kg / 81, rr = kg - ic * 81;
            float v = g_h1[base + ic * 400 + (rr / 9) * 20 + (rr % 9)];
            int s16 = __float2int_rn(v * qb);
            hi[j] = (s16 + 64) >> 7;
            lo[j] = s16 - (hi[j] << 7);
        }
        uint32_t ph = __byte_perm(__byte_perm(hi[0], hi[1], 0x0040),
                                  __byte_perm(hi[2], hi[3], 0x0040), 0x5410);
        uint32_t pl = __byte_perm(__byte_perm(lo[0], lo[1], 0x0040),
                                  __byte_perm(lo[2], lo[3], 0x0040), 0x5410);
        *(uint32_t*)(g_bqh + rowo + k0) = ph;
        *(uint32_t*)(g_bql + rowo + k0) = pl;
    }
}

// ===========================================================================
// conv2: pure int8 GEMM (2-limb, 3 MMAs per k32). Both operands cp.async.
// M=256 x N=9216 x K=20736; grid (2,144), 256 thr / 8 warps; warp tile 32x32.
// BK=64, 3-stage cp.async ring.
// D = dsA[m]*dsB[b]*(16384*HH + 128*CROSS) + bias.
// ===========================================================================
#define ROWB 80
#define PLANE_A (128 * ROWB)               // 10240
#define PLANE_B (64 * ROWB)                // 5120
#define STG (2 * PLANE_A + 2 * PLANE_B)    // 30720 per stage (Ah|Al|Bh|Bl)
#define NSTAGE 324

__global__ __launch_bounds__(256, 2) void conv2_mma_kernel(const float* __restrict__ b2) {
    extern __shared__ __align__(16) unsigned char sm[];

    const int tid = threadIdx.x, lane = tid & 31, wid = tid >> 5;
    const int m0 = blockIdx.x * 128, n0 = blockIdx.y * 64;
    const int wm0 = (wid & 3) * 32;
    const int wn0 = (wid >> 2) * 32;
    const uint32_t sb = smem_u32(sm);

    int hh[2][4][4], cr[2][4][4];
#pragma unroll
    for (int mi = 0; mi < 2; mi++)
#pragma unroll
        for (int nt = 0; nt < 4; nt++)
#pragma unroll
            for (int q = 0; q < 4; q++) { hh[mi][nt][q] = 0; cr[mi][nt][q] = 0; }

    auto issue = [&](uint32_t base, int kt) {
#pragma unroll
        for (int q = 0; q < 4; q++) {
            int id = q * 256 + tid;
            int plane = id >> 9;
            int rem = id & 511;
            int row = rem >> 2;
            int c16 = rem & 3;
            const char* src = plane ? g_w2l8 : g_w2h8;
            cp16(base + plane * PLANE_A + row * ROWB + c16 * 16,
                 src + (size_t)(m0 + row) * 20736 + kt + c16 * 16);
        }
#pragma unroll
        for (int q = 0; q < 2; q++) {
            int id = q * 256 + tid;
            int plane = id >> 8;
            int rem = id & 255;
            int row = rem >> 2;
            int c16 = rem & 3;
            const char* src = plane ? g_bql : g_bqh;
            cp16(base + 2 * PLANE_A + plane * PLANE_B + row * ROWB + c16 * 16,
                 src + (size_t)(n0 + row) * 20736 + kt + c16 * 16);
        }
        CP_COMMIT();
    };

    issue(sb, 0);
    issue(sb + STG, 64);

    for (int s = 0; s < NSTAGE; s++) {
        const uint32_t cb = sb + (uint32_t)(s % 3) * STG;
        CP_WAIT1();
        __syncthreads();
        if (s + 2 < NSTAGE) issue(sb + (uint32_t)((s + 2) % 3) * STG, (s + 2) * 64);

#pragma unroll
        for (int ks = 0; ks < 2; ks++) {
            uint32_t ah[2][4], al[2][4];
#pragma unroll
            for (int mi = 0; mi < 2; mi++) {
                uint32_t ra = (uint32_t)((wm0 + mi * 16 + (lane & 15)) * ROWB +
                                         ks * 32 + ((lane >> 4) << 4));
                ldsm_x4(ah[mi], cb + ra);
                ldsm_x4(al[mi], cb + PLANE_A + ra);
            }
            uint32_t bh[2][4], bl[2][4];
#pragma unroll
            for (int g = 0; g < 2; g++) {
                uint32_t rb = (uint32_t)((wn0 + g * 16 + (lane & 7) + ((lane >> 4) << 3)) * ROWB +
                                         ks * 32 + (((lane >> 3) & 1) << 4));
                ldsm_x4(bh[g], cb + 2 * PLANE_A + rb);
                ldsm_x4(bl[g], cb + 2 * PLANE_A + PLANE_B + rb);
            }
#pragma unroll
            for (int mi = 0; mi < 2; mi++)
#pragma unroll
                for (int g = 0; g < 2; g++)
#pragma unroll
                    for (int h = 0; h < 2; h++) {
                        int nt = g * 2 + h;
                        mma_s8(hh[mi][nt], ah[mi], bh[g][2 * h], bh[g][2 * h + 1]);
                        mma_s8(cr[mi][nt], ah[mi], bl[g][2 * h], bl[g][2 * h + 1]);
                        mma_s8(cr[mi][nt], al[mi], bh[g][2 * h], bh[g][2 * h + 1]);
                    }
        }
    }

#pragma unroll
    for (int mi = 0; mi < 2; mi++) {
        int r0 = m0 + wm0 + mi * 16 + (lane >> 2);
        int r1 = r0 + 8;
        float sa0 = g_dsA[r0], sa1 = g_dsA[r1];
        float bias0 = b2[r0], bias1 = b2[r1];
#pragma unroll
        for (int nt = 0; nt < 4; nt++) {
            int c0 = n0 + wn0 + nt * 8 + ((lane & 3) << 1);
            int c1 = c0 + 1;
            int bb0 = c0 / 36, ss0 = c0 - bb0 * 36;
            int bb1 = c1 / 36, ss1 = c1 - bb1 * 36;
            float s0 = g_dsB[bb0], s1 = g_dsB[bb1];
            g_uraw[bb0 * 9216 + ss0 + r0 * 36] =
                sa0 * s0 * (16384.f * (float)hh[mi][nt][0] + 128.f * (float)cr[mi][nt][0]) + bias0;
            g_uraw[bb1 * 9216 + ss1 + r0 * 36] =
                sa0 * s1 * (16384.f * (float)hh[mi][nt][1] + 128.f * (float)cr[mi][nt][1]) + bias0;
            g_uraw[bb0 * 9216 + ss0 + r1 * 36] =
                sa1 * s0 * (16384.f * (float)hh[mi][nt][2] + 128.f * (float)cr[mi][nt][2]) + bias1;
            g_uraw[bb1 * 9216 + ss1 + r1 * 36] =
                sa1 * s1 * (16384.f * (float)hh[mi][nt][3] + 128.f * (float)cr[mi][nt][3]) + bias1;
        }
    }
}

// ===========================================================================
// primary squash + transpose
// ===========================================================================
__global__ __launch_bounds__(256) void squashT_kernel() {
    int idx = blockIdx.x * 256 + threadIdx.x;
    int n = idx >> 8, b = idx & 255;
    const float4* src = (const float4*)&g_uraw[b * 9216 + n * 8];
    float4 u0 = src[0], u1 = src[1];
    float sq = u0.x * u0.x + u0.y * u0.y + u0.z * u0.z + u0.w * u0.w +
               u1.x * u1.x + u1.y * u1.y + u1.z * u1.z + u1.w * u1.w;
    float sc = sq / (1.0f + sq);
    float r[8] = {u0.x * sc, u0.y * sc, u0.z * sc, u0.w * sc,
                  u1.x * sc, u1.y * sc, u1.z * sc, u1.w * sc};
#pragma unroll
    for (int j = 0; j < 8; j++) g_uT[(n * 8 + j) * 256 + b] = r[j];
}

__global__ __launch_bounds__(128) void softmax_kernel() {
    int c = blockIdx.x >> 4, i = blockIdx.x & 15;
    int tid = threadIdx.x;
    __shared__ float red[128];
    float vals[9];
    float m = -1e30f;
#pragma unroll
    for (int q = 0; q < 9; q++) {
        int n = tid + q * 128;
        vals[q] = g_blog[(c * 1152 + n) * 16 + i];
        m = fmaxf(m, vals[q]);
    }
    red[tid] = m;
    __syncthreads();
    for (int s2 = 64; s2 > 0; s2 >>= 1) {
        if (tid < s2) red[tid] = fmaxf(red[tid], red[tid + s2]);
        __syncthreads();
    }
    float M = red[0];
    __syncthreads();
    float e[9];
    float sum = 0.f;
#pragma unroll
    for (int q = 0; q < 9; q++) {
        e[q] = expf(vals[q] - M);
        sum += e[q];
    }
    red[tid] = sum;
    __syncthreads();
    for (int s2 = 64; s2 > 0; s2 >>= 1) {
        if (tid < s2) red[tid] += red[tid + s2];
        __syncthreads();
    }
    float inv = 1.0f / red[0];
#pragma unroll
    for (int q = 0; q < 9; q++)
        g_probs[(c * 1152 + tid + q * 128) * 16 + i] = e[q] * inv;
}

// ===========================================================================
// s partial GEMM: 32 n-chunks of 36 (grid 320 -> better SM coverage).
// uniform=1: first routing iter, probs are 1/1152 (skip probs load).
// ===========================================================================
__global__ __launch_bounds__(128) void sgemm_routing_kernel(const float* __restrict__ W,
                                                            int uniform) {
    int nc = blockIdx.x, c = blockIdx.y;
    int tid = threadIdx.x;
    int ig = tid >> 5, bg = tid & 31;
    int i0 = ig << 2;
    __shared__ float uu[2048];
    __shared__ float pw[128];
    int pi = tid >> 3, pj = tid & 7;

    float acc[4][8];
#pragma unroll
    for (int ii = 0; ii < 4; ii++)
#pragma unroll
        for (int bi = 0; bi < 8; bi++) acc[ii][bi] = 0.f;

    for (int n = nc * 36; n < nc * 36 + 36; ++n) {
        __syncthreads();
        const float4* src = (const float4*)&g_uT[n * 2048];
#pragma unroll
        for (int q = 0; q < 4; q++) ((float4*)uu)[tid + q * 128] = src[tid + q * 128];
        float p = uniform ? (1.0f / 1152.0f) : g_probs[(c * 1152 + n) * 16 + pi];
        pw[tid] = p * W[((c * 1152 + n) * 16 + pi) * 8 + pj];
        __syncthreads();

        float pwv[4][8];
#pragma unroll
        for (int ii = 0; ii < 4; ii++)
#pragma unroll
            for (int j = 0; j < 8; j++) pwv[ii][j] = pw[(i0 + ii) * 8 + j];

#pragma unroll
        for (int bi = 0; bi < 8; bi++) {
            int b = bg + (bi << 5);
            float uv[8];
#pragma unroll
            for (int j = 0; j < 8; j++) uv[j] = uu[j * 256 + b];
#pragma unroll
            for (int ii = 0; ii < 4; ii++)
#pragma unroll
                for (int j = 0; j < 8; j++)
                    acc[ii][bi] = fmaf(pwv[ii][j], uv[j], acc[ii][bi]);
        }
    }
#pragma unroll
    for (int ii = 0; ii < 4; ii++)
#pragma unroll
        for (int bi = 0; bi < 8; bi++)
            g_spart[((c * 32 + nc) * 16 + i0 + ii) * 256 + bg + (bi << 5)] = acc[ii][bi];
}

__global__ __launch_bounds__(256) void squashv_kernel() {
    int c = blockIdx.x >> 4, i = blockIdx.x & 15;
    int tid = threadIdx.x;
    float sv = 0.f;
#pragma unroll
    for (int ch = 0; ch < 32; ch++)
        sv += g_spart[((c * 32 + ch) * 16 + i) * 256 + tid];
    __shared__ float red[256];
    red[tid] = sv * sv;
    __syncthreads();
    for (int s2 = 128; s2 > 0; s2 >>= 1) {
        if (tid < s2) red[tid] += red[tid + s2];
        __syncthreads();
    }
    float sq = red[0];
    float scale = sq / ((1.0f + sq) * sqrtf(sq));
    g_v[(c * 16 + i) * 256 + tid] = sv * scale;
}

// store=1: first delta (blog starts undefined; overwrite). Else accumulate.
__global__ __launch_bounds__(128) void delta_kernel(const float* __restrict__ W,
                                                    int store) {
    int n0 = blockIdx.x * 8, c = blockIdx.y;
    int tid = threadIdx.x;
    int nl = tid >> 4, i = tid & 15;
    int n = n0 + nl;
    __shared__ float vsh[16 * 257];
    __shared__ float ush[2048];
    float wr[8];
    const float* wp = &W[((c * 1152 + n) * 16 + i) * 8];
#pragma unroll
    for (int j = 0; j < 8; j++) wr[j] = wp[j];
#pragma unroll
    for (int q = 0; q < 32; q++) {
        int idx = tid + q * 128;
        vsh[(idx >> 8) * 257 + (idx & 255)] = g_v[c * 4096 + idx];
    }
    float acc = 0.f;
    for (int bc = 0; bc < 8; bc++) {
        __syncthreads();
#pragma unroll
        for (int q = 0; q < 16; q++) {
            int f = tid + q * 128;
            ush[f] = g_uT[(n0 * 8 + (f >> 5)) * 256 + (bc << 5) + (f & 31)];
        }
        __syncthreads();
#pragma unroll 4
        for (int bb = 0; bb < 32; bb++) {
            int b = (bc << 5) + bb;
            float uh = 0.f;
#pragma unroll
            for (int j = 0; j < 8; j++)
                uh = fmaf(wr[j], ush[(nl * 8 + j) * 32 + bb], uh);
            acc = fmaf(uh, vsh[i * 257 + b], acc);
        }
    }
    int idx = (c * 1152 + n) * 16 + i;
    g_blog[idx] = store ? acc : (g_blog[idx] + acc);
}

__global__ void out_kernel(float* __restrict__ out) {
    int c = blockIdx.x, b = threadIdx.x;
    float s = 0.f;
#pragma unroll
    for (int i = 0; i < 16; i++) {
        float t = g_v[(c * 16 + i) * 256 + b];
        s = fmaf(t, t, s);
    }
    out[b * 10 + c] = s;
}

// ===========================================================================
extern "C" void kernel_launch(void* const* d_in, const int* in_sizes, int n_in,
                              void* d_out, int out_size) {
    const float* x  = (const float*)d_in[0];
    const float* w1 = (const float*)d_in[1];
    const float* b1 = (const float*)d_in[2];
    const float* w2 = (const float*)d_in[3];
    const float* b2 = (const float*)d_in[4];
    const float* W  = (const float*)d_in[5];
    float* out = (float*)d_out;

    const int SMEM_BYTES = 3 * STG;  // 92160
    cudaFuncSetAttribute(conv2_mma_kernel, cudaFuncAttributeMaxDynamicSharedMemorySize,
                         SMEM_BYTES);

    conv1_kernel<<<dim3(256, 16), 128>>>(x, w1, b1);
    aprep_kernel<<<256, 256>>>(w2);
    bprep_kernel<<<256, 256>>>();
    bquant_kernel<<<9216, 256>>>();
    conv2_mma_kernel<<<dim3(2, 144), 256, SMEM_BYTES>>>(b2);
    squashT_kernel<<<1152, 256>>>();

    for (int it = 0; it < 3; it++) {
        if (it > 0) softmax_kernel<<<160, 128>>>();
        sgemm_routing_kernel<<<dim3(32, 10), 128>>>(W, it == 0 ? 1 : 0);
        squashv_kernel<<<160, 256>>>();
        if (it < 2) delta_kernel<<<dim3(144, 10), 128>>>(W, it == 0 ? 1 : 0);
    }
    out_kernel<<<10, 256>>>(out);
}

// round 12
// speedup vs baseline: 2.8573x; 1.0295x over previous
#include <cuda_runtime.h>
#include <math.h>
#include <stdint.h>

// ===========================================================================
// Baseline-PTX helpers (ldmatrix + mma.sync + cp.async). No tcgen05.
// ===========================================================================
__device__ __forceinline__ uint32_t smem_u32(const void* p) {
    uint32_t a;
    asm("{ .reg .u64 t; cvta.to.shared.u64 t, %1; cvt.u32.u64 %0, t; }" : "=r"(a) : "l"(p));
    return a;
}
__device__ __forceinline__ void ldsm_x4(uint32_t r[4], uint32_t addr) {
    asm volatile("ldmatrix.sync.aligned.m8n8.x4.shared.b16 {%0,%1,%2,%3}, [%4];"
                 : "=r"(r[0]), "=r"(r[1]), "=r"(r[2]), "=r"(r[3]) : "r"(addr));
}
__device__ __forceinline__ void mma_s8(int c[4], const uint32_t a[4],
                                       uint32_t b0, uint32_t b1) {
    asm volatile(
        "mma.sync.aligned.m16n8k32.row.col.s32.s8.s8.s32 "
        "{%0,%1,%2,%3}, {%4,%5,%6,%7}, {%8,%9}, {%0,%1,%2,%3};"
        : "+r"(c[0]), "+r"(c[1]), "+r"(c[2]), "+r"(c[3])
        : "r"(a[0]), "r"(a[1]), "r"(a[2]), "r"(a[3]), "r"(b0), "r"(b1));
}
__device__ __forceinline__ void cp16(uint32_t dst, const void* src) {
    asm volatile("cp.async.cg.shared.global [%0], [%1], 16;" ::"r"(dst), "l"(src));
}
#define CP_COMMIT() asm volatile("cp.async.commit_group;" ::: "memory")
#define CP_WAIT1() asm volatile("cp.async.wait_group 1;" ::: "memory")

// ===========================================================================
// Scratch (device globals)
// ===========================================================================
__device__ float g_h1[256 * 256 * 400];
__device__ float g_uraw[256 * 9216];
__device__ float g_uT[9216 * 256];
__device__ float g_blog[10 * 1152 * 16];
__device__ float g_probs[10 * 1152 * 16];
__device__ float g_spart[10 * 32 * 16 * 256];
__device__ float g_v[10 * 16 * 256];
__device__ char g_w2h8[256 * 20736];    // int8 hi limb of w2 (row-scaled)
__device__ char g_w2l8[256 * 20736];    // int8 lo limb
__device__ char g_bqh[9216 * 20736];    // im2col B, hi limb (per-batch scaled)
__device__ char g_bql[9216 * 20736];    // im2col B, lo limb
__device__ float g_dsA[256];            // dequant scale per oc row
__device__ float g_dsB[256];            // dequant scale per batch
__device__ float g_qB[256];             // quant scale per batch (16256/max)
__device__ int g_koff[20736];           // im2col k -> h1 offset (input-indep)

// ===========================================================================
// conv1 (unchanged, known-good)
// ===========================================================================
__global__ __launch_bounds__(128) void conv1_kernel(const float* __restrict__ x,
                                                    const float* __restrict__ w,
                                                    const float* __restrict__ bias) {
    int b = blockIdx.x, ocg = blockIdx.y;
    __shared__ float xs[784];
    __shared__ float ws[16 * 81];
    int tid = threadIdx.x;
    for (int i = tid; i < 784; i += 128) xs[i] = x[b * 784 + i];
    for (int i = tid; i < 1296; i += 128) ws[i] = w[ocg * 1296 + i];
    __syncthreads();

    int pr[4], pc[4];
    bool val[4];
#pragma unroll
    for (int q = 0; q < 4; q++) {
        int p = tid + q * 128;
        val[q] = (p < 400);
        int pp = val[q] ? p : 0;
        pr[q] = pp / 20;
        pc[q] = pp % 20;
    }
    float acc[4][16];
#pragma unroll
    for (int q = 0; q < 4; q++)
#pragma unroll
        for (int o = 0; o < 16; o++) acc[q][o] = 0.f;

#pragma unroll 1
    for (int kh = 0; kh < 9; kh++) {
        int rb[4];
#pragma unroll
        for (int q = 0; q < 4; q++) rb[q] = (pr[q] + kh) * 28 + pc[q];
#pragma unroll 1
        for (int kw = 0; kw < 9; kw++) {
            float xv[4];
#pragma unroll
            for (int q = 0; q < 4; q++) xv[q] = xs[rb[q] + kw];
            int ko = kh * 9 + kw;
#pragma unroll
            for (int o = 0; o < 16; o++) {
                float wv = ws[o * 81 + ko];
#pragma unroll
                for (int q = 0; q < 4; q++) acc[q][o] = fmaf(xv[q], wv, acc[q][o]);
            }
        }
    }
#pragma unroll
    for (int o = 0; o < 16; o++) {
        float bv = bias[ocg * 16 + o];
#pragma unroll
        for (int q = 0; q < 4; q++) {
            if (val[q]) {
                float v = acc[q][o] + bv;
                g_h1[(b * 256 + ocg * 16 + o) * 400 + tid + q * 128] = fmaxf(v, 0.f);
            }
        }
    }
}

// ===========================================================================
// merged prep: blocks 0-255 = A quantize (per-oc-row), 256-511 = B per-batch
// max, 512-592 = koff table build.
// ===========================================================================
__global__ __launch_bounds__(256) void prep_kernel(const float* __restrict__ w2) {
    int blk = blockIdx.x, tid = threadIdx.x;
    if (blk >= 512) {  // koff table
        int k = (blk - 512) * 256 + tid;
        if (k < 20736) {
            int ic = k / 81, rr = k - ic * 81;
            g_koff[k] = ic * 400 + (rr / 9) * 20 + (rr % 9);
        }
        return;
    }
    __shared__ float red[256];
    if (blk < 256) {  // A: row max + 2-limb quantize
        int m = blk;
        const float* row = &w2[(size_t)m * 20736];
        float mx = 0.f;
        for (int k = tid; k < 20736; k += 256) mx = fmaxf(mx, fabsf(row[k]));
        red[tid] = mx;
        __syncthreads();
        for (int s = 128; s > 0; s >>= 1) {
            if (tid < s) red[tid] = fmaxf(red[tid], red[tid + s]);
            __syncthreads();
        }
        mx = red[0];
        if (tid == 0) g_dsA[m] = mx * (1.0f / 16256.0f);
        float qa = mx > 0.f ? 16256.0f / mx : 0.f;
        for (int k = tid; k < 20736; k += 256) {
            float a15 = rintf(row[k] * qa);
            float ahf = rintf(a15 * (1.0f / 128.0f));
            int ah = (int)ahf;
            int al = (int)(a15 - 128.0f * ahf);
            g_w2h8[(size_t)m * 20736 + k] = (char)ah;
            g_w2l8[(size_t)m * 20736 + k] = (char)al;
        }
    } else {  // B: per-batch max of h1
        int b = blk - 256;
        const float* sl = &g_h1[(size_t)b * 102400];
        float mx = 0.f;
        for (int i = tid; i < 102400; i += 256) mx = fmaxf(mx, sl[i]);
        red[tid] = mx;
        __syncthreads();
        for (int s = 128; s > 0; s >>= 1) {
            if (tid < s) red[tid] = fmaxf(red[tid], red[tid + s]);
            __syncthreads();
        }
        if (tid == 0) {
            float m = red[0];
            g_dsB[b] = m * (1.0f / 16256.0f);
            g_qB[b] = m > 0.f ? 16256.0f / m : 0.f;
        }
    }
}

// ===========================================================================
// bquant: im2col B -> two int8 limb planes, via koff lookup (no divisions).
// 8 elements / thread / iteration, 64-bit packed stores.
// ===========================================================================
__global__ __launch_bounds__(256) void bquant_kernel() {
    int n = blockIdx.x;
    int bb = n / 36, s = n - bb * 36;
    int base = bb * 102400 + (s / 6) * 40 + (s % 6) * 2;
    float qb = g_qB[bb];
    size_t rowo = (size_t)n * 20736;
    const float* h1b = g_h1 + base;
    for (int k0 = threadIdx.x * 8; k0 < 20736; k0 += 2048) {
        int4 ko0 = *(const int4*)&g_koff[k0];
        int4 ko1 = *(const int4*)&g_koff[k0 + 4];
        int hi[8], lo[8];
        float v[8];
        v[0] = h1b[ko0.x]; v[1] = h1b[ko0.y]; v[2] = h1b[ko0.z]; v[3] = h1b[ko0.w];
        v[4] = h1b[ko1.x]; v[5] = h1b[ko1.y]; v[6] = h1b[ko1.z]; v[7] = h1b[ko1.w];
#pragma unroll
        for (int j = 0; j < 8; j++) {
            int s16 = __float2int_rn(v[j] * qb);
            hi[j] = (s16 + 64) >> 7;
            lo[j] = s16 - (hi[j] << 7);
        }
        uint32_t ph0 = __byte_perm(__byte_perm(hi[0], hi[1], 0x0040),
                                   __byte_perm(hi[2], hi[3], 0x0040), 0x5410);
        uint32_t ph1 = __byte_perm(__byte_perm(hi[4], hi[5], 0x0040),
                                   __byte_perm(hi[6], hi[7], 0x0040), 0x5410);
        uint32_t pl0 = __byte_perm(__byte_perm(lo[0], lo[1], 0x0040),
                                   __byte_perm(lo[2], lo[3], 0x0040), 0x5410);
        uint32_t pl1 = __byte_perm(__byte_perm(lo[4], lo[5], 0x0040),
                                   __byte_perm(lo[6], lo[7], 0x0040), 0x5410);
        *(uint2*)(g_bqh + rowo + k0) = make_uint2(ph0, ph1);
        *(uint2*)(g_bql + rowo + k0) = make_uint2(pl0, pl1);
    }
}

// ===========================================================================
// conv2: pure int8 GEMM (2-limb, 3 MMAs per k32). Both operands cp.async.
// M=256 x N=9216 x K=20736; grid (2,144), 256 thr / 8 warps; warp tile 32x32.
// BK=64, 3-stage cp.async ring.
// D = dsA[m]*dsB[b]*(16384*HH + 128*CROSS) + bias.
// ===========================================================================
#define ROWB 80
#define PLANE_A (128 * ROWB)               // 10240
#define PLANE_B (64 * ROWB)                // 5120
#define STG (2 * PLANE_A + 2 * PLANE_B)    // 30720 per stage (Ah|Al|Bh|Bl)
#define NSTAGE 324

__global__ __launch_bounds__(256, 2) void conv2_mma_kernel(const float* __restrict__ b2) {
    extern __shared__ __align__(16) unsigned char sm[];

    const int tid = threadIdx.x, lane = tid & 31, wid = tid >> 5;
    const int m0 = blockIdx.x * 128, n0 = blockIdx.y * 64;
    const int wm0 = (wid & 3) * 32;
    const int wn0 = (wid >> 2) * 32;
    const uint32_t sb = smem_u32(sm);

    int hh[2][4][4], cr[2][4][4];
#pragma unroll
    for (int mi = 0; mi < 2; mi++)
#pragma unroll
        for (int nt = 0; nt < 4; nt++)
#pragma unroll
            for (int q = 0; q < 4; q++) { hh[mi][nt][q] = 0; cr[mi][nt][q] = 0; }

    auto issue = [&](uint32_t base, int kt) {
#pragma unroll
        for (int q = 0; q < 4; q++) {
            int id = q * 256 + tid;
            int plane = id >> 9;
            int rem = id & 511;
            int row = rem >> 2;
            int c16 = rem & 3;
            const char* src = plane ? g_w2l8 : g_w2h8;
            cp16(base + plane * PLANE_A + row * ROWB + c16 * 16,
                 src + (size_t)(m0 + row) * 20736 + kt + c16 * 16);
        }
#pragma unroll
        for (int q = 0; q < 2; q++) {
            int id = q * 256 + tid;
            int plane = id >> 8;
            int rem = id & 255;
            int row = rem >> 2;
            int c16 = rem & 3;
            const char* src = plane ? g_bql : g_bqh;
            cp16(base + 2 * PLANE_A + plane * PLANE_B + row * ROWB + c16 * 16,
                 src + (size_t)(n0 + row) * 20736 + kt + c16 * 16);
        }
        CP_COMMIT();
    };

    issue(sb, 0);
    issue(sb + STG, 64);

    for (int s = 0; s < NSTAGE; s++) {
        const uint32_t cb = sb + (uint32_t)(s % 3) * STG;
        CP_WAIT1();
        __syncthreads();
        if (s + 2 < NSTAGE) issue(sb + (uint32_t)((s + 2) % 3) * STG, (s + 2) * 64);

#pragma unroll
        for (int ks = 0; ks < 2; ks++) {
            uint32_t ah[2][4], al[2][4];
#pragma unroll
            for (int mi = 0; mi < 2; mi++) {
                uint32_t ra = (uint32_t)((wm0 + mi * 16 + (lane & 15)) * ROWB +
                                         ks * 32 + ((lane >> 4) << 4));
                ldsm_x4(ah[mi], cb + ra);
                ldsm_x4(al[mi], cb + PLANE_A + ra);
            }
            uint32_t bh[2][4], bl[2][4];
#pragma unroll
            for (int g = 0; g < 2; g++) {
                uint32_t rb = (uint32_t)((wn0 + g * 16 + (lane & 7) + ((lane >> 4) << 3)) * ROWB +
                                         ks * 32 + (((lane >> 3) & 1) << 4));
                ldsm_x4(bh[g], cb + 2 * PLANE_A + rb);
                ldsm_x4(bl[g], cb + 2 * PLANE_A + PLANE_B + rb);
            }
#pragma unroll
            for (int mi = 0; mi < 2; mi++)
#pragma unroll
                for (int g = 0; g < 2; g++)
#pragma unroll
                    for (int h = 0; h < 2; h++) {
                        int nt = g * 2 + h;
                        mma_s8(hh[mi][nt], ah[mi], bh[g][2 * h], bh[g][2 * h + 1]);
                        mma_s8(cr[mi][nt], ah[mi], bl[g][2 * h], bl[g][2 * h + 1]);
                        mma_s8(cr[mi][nt], al[mi], bh[g][2 * h], bh[g][2 * h + 1]);
                    }
        }
    }

#pragma unroll
    for (int mi = 0; mi < 2; mi++) {
        int r0 = m0 + wm0 + mi * 16 + (lane >> 2);
        int r1 = r0 + 8;
        float sa0 = g_dsA[r0], sa1 = g_dsA[r1];
        float bias0 = b2[r0], bias1 = b2[r1];
#pragma unroll
        for (int nt = 0; nt < 4; nt++) {
            int c0 = n0 + wn0 + nt * 8 + ((lane & 3) << 1);
            int c1 = c0 + 1;
            int bb0 = c0 / 36, ss0 = c0 - bb0 * 36;
            int bb1 = c1 / 36, ss1 = c1 - bb1 * 36;
            float s0 = g_dsB[bb0], s1 = g_dsB[bb1];
            g_uraw[bb0 * 9216 + ss0 + r0 * 36] =
                sa0 * s0 * (16384.f * (float)hh[mi][nt][0] + 128.f * (float)cr[mi][nt][0]) + bias0;
            g_uraw[bb1 * 9216 + ss1 + r0 * 36] =
                sa0 * s1 * (16384.f * (float)hh[mi][nt][1] + 128.f * (float)cr[mi][nt][1]) + bias0;
            g_uraw[bb0 * 9216 + ss0 + r1 * 36] =
                sa1 * s0 * (16384.f * (float)hh[mi][nt][2] + 128.f * (float)cr[mi][nt][2]) + bias1;
            g_uraw[bb1 * 9216 + ss1 + r1 * 36] =
                sa1 * s1 * (16384.f * (float)hh[mi][nt][3] + 128.f * (float)cr[mi][nt][3]) + bias1;
        }
    }
}

// ===========================================================================
// primary squash + transpose
// ===========================================================================
__global__ __launch_bounds__(256) void squashT_kernel() {
    int idx = blockIdx.x * 256 + threadIdx.x;
    int n = idx >> 8, b = idx & 255;
    const float4* src = (const float4*)&g_uraw[b * 9216 + n * 8];
    float4 u0 = src[0], u1 = src[1];
    float sq = u0.x * u0.x + u0.y * u0.y + u0.z * u0.z + u0.w * u0.w +
               u1.x * u1.x + u1.y * u1.y + u1.z * u1.z + u1.w * u1.w;
    float sc = sq / (1.0f + sq);
    float r[8] = {u0.x * sc, u0.y * sc, u0.z * sc, u0.w * sc,
                  u1.x * sc, u1.y * sc, u1.z * sc, u1.w * sc};
#pragma unroll
    for (int j = 0; j < 8; j++) g_uT[(n * 8 + j) * 256 + b] = r[j];
}

__global__ __launch_bounds__(128) void softmax_kernel() {
    int c = blockIdx.x >> 4, i = blockIdx.x & 15;
    int tid = threadIdx.x;
    __shared__ float red[128];
    float vals[9];
    float m = -1e30f;
#pragma unroll
    for (int q = 0; q < 9; q++) {
        int n = tid + q * 128;
        vals[q] = g_blog[(c * 1152 + n) * 16 + i];
        m = fmaxf(m, vals[q]);
    }
    red[tid] = m;
    __syncthreads();
    for (int s2 = 64; s2 > 0; s2 >>= 1) {
        if (tid < s2) red[tid] = fmaxf(red[tid], red[tid + s2]);
        __syncthreads();
    }
    float M = red[0];
    __syncthreads();
    float e[9];
    float sum = 0.f;
#pragma unroll
    for (int q = 0; q < 9; q++) {
        e[q] = expf(vals[q] - M);
        sum += e[q];
    }
    red[tid] = sum;
    __syncthreads();
    for (int s2 = 64; s2 > 0; s2 >>= 1) {
        if (tid < s2) red[tid] += red[tid + s2];
        __syncthreads();
    }
    float inv = 1.0f / red[0];
#pragma unroll
    for (int q = 0; q < 9; q++)
        g_probs[(c * 1152 + tid + q * 128) * 16 + i] = e[q] * inv;
}

// ===========================================================================
// s partial GEMM: 32 n-chunks of 36. uniform=1: probs = 1/1152 (iter 0).
// ===========================================================================
__global__ __launch_bounds__(128) void sgemm_routing_kernel(const float* __restrict__ W,
                                                            int uniform) {
    int nc = blockIdx.x, c = blockIdx.y;
    int tid = threadIdx.x;
    int ig = tid >> 5, bg = tid & 31;
    int i0 = ig << 2;
    __shared__ float uu[2048];
    __shared__ float pw[128];
    int pi = tid >> 3, pj = tid & 7;

    float acc[4][8];
#pragma unroll
    for (int ii = 0; ii < 4; ii++)
#pragma unroll
        for (int bi = 0; bi < 8; bi++) acc[ii][bi] = 0.f;

    for (int n = nc * 36; n < nc * 36 + 36; ++n) {
        __syncthreads();
        const float4* src = (const float4*)&g_uT[n * 2048];
#pragma unroll
        for (int q = 0; q < 4; q++) ((float4*)uu)[tid + q * 128] = src[tid + q * 128];
        float p = uniform ? (1.0f / 1152.0f) : g_probs[(c * 1152 + n) * 16 + pi];
        pw[tid] = p * W[((c * 1152 + n) * 16 + pi) * 8 + pj];
        __syncthreads();

        float pwv[4][8];
#pragma unroll
        for (int ii = 0; ii < 4; ii++)
#pragma unroll
            for (int j = 0; j < 8; j++) pwv[ii][j] = pw[(i0 + ii) * 8 + j];

#pragma unroll
        for (int bi = 0; bi < 8; bi++) {
            int b = bg + (bi << 5);
            float uv[8];
#pragma unroll
            for (int j = 0; j < 8; j++) uv[j] = uu[j * 256 + b];
#pragma unroll
            for (int ii = 0; ii < 4; ii++)
#pragma unroll
                for (int j = 0; j < 8; j++)
                    acc[ii][bi] = fmaf(pwv[ii][j], uv[j], acc[ii][bi]);
        }
    }
#pragma unroll
    for (int ii = 0; ii < 4; ii++)
#pragma unroll
        for (int bi = 0; bi < 8; bi++)
            g_spart[((c * 32 + nc) * 16 + i0 + ii) * 256 + bg + (bi << 5)] = acc[ii][bi];
}

__global__ __launch_bounds__(256) void squashv_kernel() {
    int c = blockIdx.x >> 4, i = blockIdx.x & 15;
    int tid = threadIdx.x;
    float sv = 0.f;
#pragma unroll
    for (int ch = 0; ch < 32; ch++)
        sv += g_spart[((c * 32 + ch) * 16 + i) * 256 + tid];
    __shared__ float red[256];
    red[tid] = sv * sv;
    __syncthreads();
    for (int s2 = 128; s2 > 0; s2 >>= 1) {
        if (tid < s2) red[tid] += red[tid + s2];
        __syncthreads();
    }
    float sq = red[0];
    float scale = sq / ((1.0f + sq) * sqrtf(sq));
    g_v[(c * 16 + i) * 256 + tid] = sv * scale;
}

// store=1: first delta (blog starts undefined; overwrite). Else accumulate.
__global__ __launch_bounds__(128) void delta_kernel(const float* __restrict__ W,
                                                    int store) {
    int n0 = blockIdx.x * 8, c = blockIdx.y;
    int tid = threadIdx.x;
    int nl = tid >> 4, i = tid & 15;
    int n = n0 + nl;
    __shared__ float vsh[16 * 257];
    __shared__ float ush[2048];
    float wr[8];
    const float* wp = &W[((c * 1152 + n) * 16 + i) * 8];
#pragma unroll
    for (int j = 0; j < 8; j++) wr[j] = wp[j];
#pragma unroll
    for (int q = 0; q < 32; q++) {
        int idx = tid + q * 128;
        vsh[(idx >> 8) * 257 + (idx & 255)] = g_v[c * 4096 + idx];
    }
    float acc = 0.f;
    for (int bc = 0; bc < 8; bc++) {
        __syncthreads();
#pragma unroll
        for (int q = 0; q < 16; q++) {
            int f = tid + q * 128;
            ush[f] = g_uT[(n0 * 8 + (f >> 5)) * 256 + (bc << 5) + (f & 31)];
        }
        __syncthreads();
#pragma unroll 4
        for (int bb = 0; bb < 32; bb++) {
            int b = (bc << 5) + bb;
            float uh = 0.f;
#pragma unroll
            for (int j = 0; j < 8; j++)
                uh = fmaf(wr[j], ush[(nl * 8 + j) * 32 + bb], uh);
            acc = fmaf(uh, vsh[i * 257 + b], acc);
        }
    }
    int idx = (c * 1152 + n) * 16 + i;
    g_blog[idx] = store ? acc : (g_blog[idx] + acc);
}

__global__ void out_kernel(float* __restrict__ out) {
    int c = blockIdx.x, b = threadIdx.x;
    float s = 0.f;
#pragma unroll
    for (int i = 0; i < 16; i++) {
        float t = g_v[(c * 16 + i) * 256 + b];
        s = fmaf(t, t, s);
    }
    out[b * 10 + c] = s;
}

// ===========================================================================
extern "C" void kernel_launch(void* const* d_in, const int* in_sizes, int n_in,
                              void* d_out, int out_size) {
    const float* x  = (const float*)d_in[0];
    const float* w1 = (const float*)d_in[1];
    const float* b1 = (const float*)d_in[2];
    const float* w2 = (const float*)d_in[3];
    const float* b2 = (const float*)d_in[4];
    const float* W  = (const float*)d_in[5];
    float* out = (float*)d_out;

    const int SMEM_BYTES = 3 * STG;  // 92160
    cudaFuncSetAttribute(conv2_mma_kernel, cudaFuncAttributeMaxDynamicSharedMemorySize,
                         SMEM_BYTES);

    conv1_kernel<<<dim3(256, 16), 128>>>(x, w1, b1);
    prep_kernel<<<593, 256>>>(w2);
    bquant_kernel<<<9216, 256>>>();
    conv2_mma_kernel<<<dim3(2, 144), 256, SMEM_BYTES>>>(b2);  // 4th launch -> profiled
    squashT_kernel<<<1152, 256>>>();

    for (int it = 0; it < 3; it++) {
        if (it > 0) softmax_kernel<<<160, 128>>>();
        sgemm_routing_kernel<<<dim3(32, 10), 128>>>(W, it == 0 ? 1 : 0);
        squashv_kernel<<<160, 256>>>();
        if (it < 2) delta_kernel<<<dim3(144, 10), 128>>>(W, it == 0 ? 1 : 0);
    }
    out_kernel<<<10, 256>>>(out);
}

// round 13
// speedup vs baseline: 2.8609x; 1.0012x over previous
#include <cuda_runtime.h>
#include <math.h>
#include <stdint.h>

// ===========================================================================
// Baseline-PTX helpers (ldmatrix + mma.sync + cp.async). No tcgen05.
// ===========================================================================
__device__ __forceinline__ uint32_t smem_u32(const void* p) {
    uint32_t a;
    asm("{ .reg .u64 t; cvta.to.shared.u64 t, %1; cvt.u32.u64 %0, t; }" : "=r"(a) : "l"(p));
    return a;
}
__device__ __forceinline__ void ldsm_x4(uint32_t r[4], uint32_t addr) {
    asm volatile("ldmatrix.sync.aligned.m8n8.x4.shared.b16 {%0,%1,%2,%3}, [%4];"
                 : "=r"(r[0]), "=r"(r[1]), "=r"(r[2]), "=r"(r[3]) : "r"(addr));
}
__device__ __forceinline__ void mma_s8(int c[4], const uint32_t a[4],
                                       uint32_t b0, uint32_t b1) {
    asm volatile(
        "mma.sync.aligned.m16n8k32.row.col.s32.s8.s8.s32 "
        "{%0,%1,%2,%3}, {%4,%5,%6,%7}, {%8,%9}, {%0,%1,%2,%3};"
        : "+r"(c[0]), "+r"(c[1]), "+r"(c[2]), "+r"(c[3])
        : "r"(a[0]), "r"(a[1]), "r"(a[2]), "r"(a[3]), "r"(b0), "r"(b1));
}
__device__ __forceinline__ void cp16(uint32_t dst, const void* src) {
    asm volatile("cp.async.cg.shared.global [%0], [%1], 16;" ::"r"(dst), "l"(src));
}
#define CP_COMMIT() asm volatile("cp.async.commit_group;" ::: "memory")
#define CP_WAIT1() asm volatile("cp.async.wait_group 1;" ::: "memory")

// ===========================================================================
// Scratch (device globals)
// ===========================================================================
__device__ float g_h1[256 * 256 * 400];
__device__ float g_uraw[256 * 9216];
__device__ float g_uT[9216 * 256];
__device__ float g_blog[10 * 1152 * 16];
__device__ float g_probs[10 * 1152 * 16];
__device__ float g_spart[10 * 32 * 16 * 256];
__device__ float g_v[10 * 16 * 256];
__device__ char g_w2h8[256 * 20736];    // int8 hi limb of w2 (row-scaled)
__device__ char g_w2l8[256 * 20736];    // int8 lo limb
__device__ char g_bqh[9216 * 20736];    // im2col B, hi limb (per-batch scaled)
__device__ char g_bql[9216 * 20736];    // im2col B, lo limb
__device__ float g_dsA[256];            // dequant scale per oc row
__device__ float g_dsB[256];            // dequant scale per batch
__device__ float g_qB[256];             // quant scale per batch (16256/max)
__device__ int g_koff[20736];           // im2col k -> h1 offset (input-indep)

// ===========================================================================
// conv1 (unchanged, known-good)
// ===========================================================================
__global__ __launch_bounds__(128) void conv1_kernel(const float* __restrict__ x,
                                                    const float* __restrict__ w,
                                                    const float* __restrict__ bias) {
    int b = blockIdx.x, ocg = blockIdx.y;
    __shared__ float xs[784];
    __shared__ float ws[16 * 81];
    int tid = threadIdx.x;
    for (int i = tid; i < 784; i += 128) xs[i] = x[b * 784 + i];
    for (int i = tid; i < 1296; i += 128) ws[i] = w[ocg * 1296 + i];
    __syncthreads();

    int pr[4], pc[4];
    bool val[4];
#pragma unroll
    for (int q = 0; q < 4; q++) {
        int p = tid + q * 128;
        val[q] = (p < 400);
        int pp = val[q] ? p : 0;
        pr[q] = pp / 20;
        pc[q] = pp % 20;
    }
    float acc[4][16];
#pragma unroll
    for (int q = 0; q < 4; q++)
#pragma unroll
        for (int o = 0; o < 16; o++) acc[q][o] = 0.f;

#pragma unroll 1
    for (int kh = 0; kh < 9; kh++) {
        int rb[4];
#pragma unroll
        for (int q = 0; q < 4; q++) rb[q] = (pr[q] + kh) * 28 + pc[q];
#pragma unroll 1
        for (int kw = 0; kw < 9; kw++) {
            float xv[4];
#pragma unroll
            for (int q = 0; q < 4; q++) xv[q] = xs[rb[q] + kw];
            int ko = kh * 9 + kw;
#pragma unroll
            for (int o = 0; o < 16; o++) {
                float wv = ws[o * 81 + ko];
#pragma unroll
                for (int q = 0; q < 4; q++) acc[q][o] = fmaf(xv[q], wv, acc[q][o]);
            }
        }
    }
#pragma unroll
    for (int o = 0; o < 16; o++) {
        float bv = bias[ocg * 16 + o];
#pragma unroll
        for (int q = 0; q < 4; q++) {
            if (val[q]) {
                float v = acc[q][o] + bv;
                g_h1[(b * 256 + ocg * 16 + o) * 400 + tid + q * 128] = fmaxf(v, 0.f);
            }
        }
    }
}

// ===========================================================================
// merged prep: blocks 0-255 = A quantize (per-oc-row), 256-511 = B per-batch
// max, 512-592 = koff table build.
// ===========================================================================
__global__ __launch_bounds__(256) void prep_kernel(const float* __restrict__ w2) {
    int blk = blockIdx.x, tid = threadIdx.x;
    if (blk >= 512) {  // koff table
        int k = (blk - 512) * 256 + tid;
        if (k < 20736) {
            int ic = k / 81, rr = k - ic * 81;
            g_koff[k] = ic * 400 + (rr / 9) * 20 + (rr % 9);
        }
        return;
    }
    __shared__ float red[256];
    if (blk < 256) {  // A: row max + 2-limb quantize
        int m = blk;
        const float* row = &w2[(size_t)m * 20736];
        float mx = 0.f;
        for (int k = tid; k < 20736; k += 256) mx = fmaxf(mx, fabsf(row[k]));
        red[tid] = mx;
        __syncthreads();
        for (int s = 128; s > 0; s >>= 1) {
            if (tid < s) red[tid] = fmaxf(red[tid], red[tid + s]);
            __syncthreads();
        }
        mx = red[0];
        if (tid == 0) g_dsA[m] = mx * (1.0f / 16256.0f);
        float qa = mx > 0.f ? 16256.0f / mx : 0.f;
        for (int k = tid; k < 20736; k += 256) {
            float a15 = rintf(row[k] * qa);
            float ahf = rintf(a15 * (1.0f / 128.0f));
            int ah = (int)ahf;
            int al = (int)(a15 - 128.0f * ahf);
            g_w2h8[(size_t)m * 20736 + k] = (char)ah;
            g_w2l8[(size_t)m * 20736 + k] = (char)al;
        }
    } else {  // B: per-batch max of h1
        int b = blk - 256;
        const float* sl = &g_h1[(size_t)b * 102400];
        float mx = 0.f;
        for (int i = tid; i < 102400; i += 256) mx = fmaxf(mx, sl[i]);
        red[tid] = mx;
        __syncthreads();
        for (int s = 128; s > 0; s >>= 1) {
            if (tid < s) red[tid] = fmaxf(red[tid], red[tid + s]);
            __syncthreads();
        }
        if (tid == 0) {
            float m = red[0];
            g_dsB[b] = m * (1.0f / 16256.0f);
            g_qB[b] = m > 0.f ? 16256.0f / m : 0.f;
        }
    }
}

// ===========================================================================
// bquant: im2col B -> two int8 limb planes, via koff lookup (no divisions).
// ===========================================================================
__global__ __launch_bounds__(256) void bquant_kernel() {
    int n = blockIdx.x;
    int bb = n / 36, s = n - bb * 36;
    int base = bb * 102400 + (s / 6) * 40 + (s % 6) * 2;
    float qb = g_qB[bb];
    size_t rowo = (size_t)n * 20736;
    const float* h1b = g_h1 + base;
    for (int k0 = threadIdx.x * 8; k0 < 20736; k0 += 2048) {
        int4 ko0 = *(const int4*)&g_koff[k0];
        int4 ko1 = *(const int4*)&g_koff[k0 + 4];
        int hi[8], lo[8];
        float v[8];
        v[0] = h1b[ko0.x]; v[1] = h1b[ko0.y]; v[2] = h1b[ko0.z]; v[3] = h1b[ko0.w];
        v[4] = h1b[ko1.x]; v[5] = h1b[ko1.y]; v[6] = h1b[ko1.z]; v[7] = h1b[ko1.w];
#pragma unroll
        for (int j = 0; j < 8; j++) {
            int s16 = __float2int_rn(v[j] * qb);
            hi[j] = (s16 + 64) >> 7;
            lo[j] = s16 - (hi[j] << 7);
        }
        uint32_t ph0 = __byte_perm(__byte_perm(hi[0], hi[1], 0x0040),
                                   __byte_perm(hi[2], hi[3], 0x0040), 0x5410);
        uint32_t ph1 = __byte_perm(__byte_perm(hi[4], hi[5], 0x0040),
                                   __byte_perm(hi[6], hi[7], 0x0040), 0x5410);
        uint32_t pl0 = __byte_perm(__byte_perm(lo[0], lo[1], 0x0040),
                                   __byte_perm(lo[2], lo[3], 0x0040), 0x5410);
        uint32_t pl1 = __byte_perm(__byte_perm(lo[4], lo[5], 0x0040),
                                   __byte_perm(lo[6], lo[7], 0x0040), 0x5410);
        *(uint2*)(g_bqh + rowo + k0) = make_uint2(ph0, ph1);
        *(uint2*)(g_bql + rowo + k0) = make_uint2(pl0, pl1);
    }
}

// ===========================================================================
// conv2: pure int8 GEMM (2-limb, 3 MMAs per k32), pass-reordered to break
// accumulator RAW chains (hh sweep, ah*bl sweep, al*bh sweep).
// M=256 x N=9216 x K=20736; grid (2,144), 256 thr / 8 warps; warp tile 32x32.
// BK=64, 3-stage cp.async ring.
// ===========================================================================
#define ROWB 80
#define PLANE_A (128 * ROWB)               // 10240
#define PLANE_B (64 * ROWB)                // 5120
#define STG (2 * PLANE_A + 2 * PLANE_B)    // 30720 per stage (Ah|Al|Bh|Bl)
#define NSTAGE 324

__global__ __launch_bounds__(256, 2) void conv2_mma_kernel(const float* __restrict__ b2) {
    extern __shared__ __align__(16) unsigned char sm[];

    const int tid = threadIdx.x, lane = tid & 31, wid = tid >> 5;
    const int m0 = blockIdx.x * 128, n0 = blockIdx.y * 64;
    const int wm0 = (wid & 3) * 32;
    const int wn0 = (wid >> 2) * 32;
    const uint32_t sb = smem_u32(sm);

    int hh[2][4][4], cr[2][4][4];
#pragma unroll
    for (int mi = 0; mi < 2; mi++)
#pragma unroll
        for (int nt = 0; nt < 4; nt++)
#pragma unroll
            for (int q = 0; q < 4; q++) { hh[mi][nt][q] = 0; cr[mi][nt][q] = 0; }

    auto issue = [&](uint32_t base, int kt) {
#pragma unroll
        for (int q = 0; q < 4; q++) {
            int id = q * 256 + tid;
            int plane = id >> 9;
            int rem = id & 511;
            int row = rem >> 2;
            int c16 = rem & 3;
            const char* src = plane ? g_w2l8 : g_w2h8;
            cp16(base + plane * PLANE_A + row * ROWB + c16 * 16,
                 src + (size_t)(m0 + row) * 20736 + kt + c16 * 16);
        }
#pragma unroll
        for (int q = 0; q < 2; q++) {
            int id = q * 256 + tid;
            int plane = id >> 8;
            int rem = id & 255;
            int row = rem >> 2;
            int c16 = rem & 3;
            const char* src = plane ? g_bql : g_bqh;
            cp16(base + 2 * PLANE_A + plane * PLANE_B + row * ROWB + c16 * 16,
                 src + (size_t)(n0 + row) * 20736 + kt + c16 * 16);
        }
        CP_COMMIT();
    };

    issue(sb, 0);
    issue(sb + STG, 64);

    for (int s = 0; s < NSTAGE; s++) {
        const uint32_t cb = sb + (uint32_t)(s % 3) * STG;
        CP_WAIT1();
        __syncthreads();
        if (s + 2 < NSTAGE) issue(sb + (uint32_t)((s + 2) % 3) * STG, (s + 2) * 64);

#pragma unroll
        for (int ks = 0; ks < 2; ks++) {
            uint32_t ah[2][4], al[2][4];
#pragma unroll
            for (int mi = 0; mi < 2; mi++) {
                uint32_t ra = (uint32_t)((wm0 + mi * 16 + (lane & 15)) * ROWB +
                                         ks * 32 + ((lane >> 4) << 4));
                ldsm_x4(ah[mi], cb + ra);
                ldsm_x4(al[mi], cb + PLANE_A + ra);
            }
            uint32_t bh[2][4], bl[2][4];
#pragma unroll
            for (int g = 0; g < 2; g++) {
                uint32_t rb = (uint32_t)((wn0 + g * 16 + (lane & 7) + ((lane >> 4) << 3)) * ROWB +
                                         ks * 32 + (((lane >> 3) & 1) << 4));
                ldsm_x4(bh[g], cb + 2 * PLANE_A + rb);
                ldsm_x4(bl[g], cb + 2 * PLANE_A + PLANE_B + rb);
            }
            // pass 1: hh += ah*bh (8 independent MMAs)
#pragma unroll
            for (int mi = 0; mi < 2; mi++)
#pragma unroll
                for (int g = 0; g < 2; g++)
#pragma unroll
                    for (int h = 0; h < 2; h++)
                        mma_s8(hh[mi][g * 2 + h], ah[mi], bh[g][2 * h], bh[g][2 * h + 1]);
            // pass 2: cr += ah*bl (8 independent MMAs)
#pragma unroll
            for (int mi = 0; mi < 2; mi++)
#pragma unroll
                for (int g = 0; g < 2; g++)
#pragma unroll
                    for (int h = 0; h < 2; h++)
                        mma_s8(cr[mi][g * 2 + h], ah[mi], bl[g][2 * h], bl[g][2 * h + 1]);
            // pass 3: cr += al*bh (RAW vs pass 2 separated by 8 MMAs)
#pragma unroll
            for (int mi = 0; mi < 2; mi++)
#pragma unroll
                for (int g = 0; g < 2; g++)
#pragma unroll
                    for (int h = 0; h < 2; h++)
                        mma_s8(cr[mi][g * 2 + h], al[mi], bh[g][2 * h], bh[g][2 * h + 1]);
        }
    }

#pragma unroll
    for (int mi = 0; mi < 2; mi++) {
        int r0 = m0 + wm0 + mi * 16 + (lane >> 2);
        int r1 = r0 + 8;
        float sa0 = g_dsA[r0], sa1 = g_dsA[r1];
        float bias0 = b2[r0], bias1 = b2[r1];
#pragma unroll
        for (int nt = 0; nt < 4; nt++) {
            int c0 = n0 + wn0 + nt * 8 + ((lane & 3) << 1);
            int c1 = c0 + 1;
            int bb0 = c0 / 36, ss0 = c0 - bb0 * 36;
            int bb1 = c1 / 36, ss1 = c1 - bb1 * 36;
            float s0 = g_dsB[bb0], s1 = g_dsB[bb1];
            g_uraw[bb0 * 9216 + ss0 + r0 * 36] =
                sa0 * s0 * (16384.f * (float)hh[mi][nt][0] + 128.f * (float)cr[mi][nt][0]) + bias0;
            g_uraw[bb1 * 9216 + ss1 + r0 * 36] =
                sa0 * s1 * (16384.f * (float)hh[mi][nt][1] + 128.f * (float)cr[mi][nt][1]) + bias0;
            g_uraw[bb0 * 9216 + ss0 + r1 * 36] =
                sa1 * s0 * (16384.f * (float)hh[mi][nt][2] + 128.f * (float)cr[mi][nt][2]) + bias1;
            g_uraw[bb1 * 9216 + ss1 + r1 * 36] =
                sa1 * s1 * (16384.f * (float)hh[mi][nt][3] + 128.f * (float)cr[mi][nt][3]) + bias1;
        }
    }
}

// ===========================================================================
// primary squash + transpose
// ===========================================================================
__global__ __launch_bounds__(256) void squashT_kernel() {
    int idx = blockIdx.x * 256 + threadIdx.x;
    int n = idx >> 8, b = idx & 255;
    const float4* src = (const float4*)&g_uraw[b * 9216 + n * 8];
    float4 u0 = src[0], u1 = src[1];
    float sq = u0.x * u0.x + u0.y * u0.y + u0.z * u0.z + u0.w * u0.w +
               u1.x * u1.x + u1.y * u1.y + u1.z * u1.z + u1.w * u1.w;
    float sc = sq / (1.0f + sq);
    float r[8] = {u0.x * sc, u0.y * sc, u0.z * sc, u0.w * sc,
                  u1.x * sc, u1.y * sc, u1.z * sc, u1.w * sc};
#pragma unroll
    for (int j = 0; j < 8; j++) g_uT[(n * 8 + j) * 256 + b] = r[j];
}

__global__ __launch_bounds__(128) void softmax_kernel() {
    int c = blockIdx.x >> 4, i = blockIdx.x & 15;
    int tid = threadIdx.x;
    __shared__ float red[128];
    float vals[9];
    float m = -1e30f;
#pragma unroll
    for (int q = 0; q < 9; q++) {
        int n = tid + q * 128;
        vals[q] = g_blog[(c * 1152 + n) * 16 + i];
        m = fmaxf(m, vals[q]);
    }
    red[tid] = m;
    __syncthreads();
    for (int s2 = 64; s2 > 0; s2 >>= 1) {
        if (tid < s2) red[tid] = fmaxf(red[tid], red[tid + s2]);
        __syncthreads();
    }
    float M = red[0];
    __syncthreads();
    float e[9];
    float sum = 0.f;
#pragma unroll
    for (int q = 0; q < 9; q++) {
        e[q] = expf(vals[q] - M);
        sum += e[q];
    }
    red[tid] = sum;
    __syncthreads();
    for (int s2 = 64; s2 > 0; s2 >>= 1) {
        if (tid < s2) red[tid] += red[tid + s2];
        __syncthreads();
    }
    float inv = 1.0f / red[0];
#pragma unroll
    for (int q = 0; q < 9; q++)
        g_probs[(c * 1152 + tid + q * 128) * 16 + i] = e[q] * inv;
}

// ===========================================================================
// s partial GEMM: 32 n-chunks of 36. uniform=1: probs = 1/1152 (iter 0).
// ===========================================================================
__global__ __launch_bounds__(128) void sgemm_routing_kernel(const float* __restrict__ W,
                                                            int uniform) {
    int nc = blockIdx.x, c = blockIdx.y;
    int tid = threadIdx.x;
    int ig = tid >> 5, bg = tid & 31;
    int i0 = ig << 2;
    __shared__ float uu[2048];
    __shared__ float pw[128];
    int pi = tid >> 3, pj = tid & 7;

    float acc[4][8];
#pragma unroll
    for (int ii = 0; ii < 4; ii++)
#pragma unroll
        for (int bi = 0; bi < 8; bi++) acc[ii][bi] = 0.f;

    for (int n = nc * 36; n < nc * 36 + 36; ++n) {
        __syncthreads();
        const float4* src = (const float4*)&g_uT[n * 2048];
#pragma unroll
        for (int q = 0; q < 4; q++) ((float4*)uu)[tid + q * 128] = src[tid + q * 128];
        float p = uniform ? (1.0f / 1152.0f) : g_probs[(c * 1152 + n) * 16 + pi];
        pw[tid] = p * W[((c * 1152 + n) * 16 + pi) * 8 + pj];
        __syncthreads();

        float pwv[4][8];
#pragma unroll
        for (int ii = 0; ii < 4; ii++)
#pragma unroll
            for (int j = 0; j < 8; j++) pwv[ii][j] = pw[(i0 + ii) * 8 + j];

#pragma unroll
        for (int bi = 0; bi < 8; bi++) {
            int b = bg + (bi << 5);
            float uv[8];
#pragma unroll
            for (int j = 0; j < 8; j++) uv[j] = uu[j * 256 + b];
#pragma unroll
            for (int ii = 0; ii < 4; ii++)
#pragma unroll
                for (int j = 0; j < 8; j++)
                    acc[ii][bi] = fmaf(pwv[ii][j], uv[j], acc[ii][bi]);
        }
    }
#pragma unroll
    for (int ii = 0; ii < 4; ii++)
#pragma unroll
        for (int bi = 0; bi < 8; bi++)
            g_spart[((c * 32 + nc) * 16 + i0 + ii) * 256 + bg + (bi << 5)] = acc[ii][bi];
}

__global__ __launch_bounds__(256) void squashv_kernel() {
    int c = blockIdx.x >> 4, i = blockIdx.x & 15;
    int tid = threadIdx.x;
    float sv = 0.f;
#pragma unroll
    for (int ch = 0; ch < 32; ch++)
        sv += g_spart[((c * 32 + ch) * 16 + i) * 256 + tid];
    __shared__ float red[256];
    red[tid] = sv * sv;
    __syncthreads();
    for (int s2 = 128; s2 > 0; s2 >>= 1) {
        if (tid < s2) red[tid] += red[tid + s2];
        __syncthreads();
    }
    float sq = red[0];
    float scale = sq / ((1.0f + sq) * sqrtf(sq));
    g_v[(c * 16 + i) * 256 + tid] = sv * scale;
}

// store=1: first delta (blog starts undefined; overwrite). Else accumulate.
__global__ __launch_bounds__(128) void delta_kernel(const float* __restrict__ W,
                                                    int store) {
    int n0 = blockIdx.x * 8, c = blockIdx.y;
    int tid = threadIdx.x;
    int nl = tid >> 4, i = tid & 15;
    int n = n0 + nl;
    __shared__ float vsh[16 * 257];
    __shared__ float ush[2048];
    float wr[8];
    const float* wp = &W[((c * 1152 + n) * 16 + i) * 8];
#pragma unroll
    for (int j = 0; j < 8; j++) wr[j] = wp[j];
#pragma unroll
    for (int q = 0; q < 32; q++) {
        int idx = tid + q * 128;
        vsh[(idx >> 8) * 257 + (idx & 255)] = g_v[c * 4096 + idx];
    }
    float acc = 0.f;
    for (int bc = 0; bc < 8; bc++) {
        __syncthreads();
#pragma unroll
        for (int q = 0; q < 16; q++) {
            int f = tid + q * 128;
            ush[f] = g_uT[(n0 * 8 + (f >> 5)) * 256 + (bc << 5) + (f & 31)];
        }
        __syncthreads();
#pragma unroll 4
        for (int bb = 0; bb < 32; bb++) {
            int b = (bc << 5) + bb;
            float uh = 0.f;
#pragma unroll
            for (int j = 0; j < 8; j++)
                uh = fmaf(wr[j], ush[(nl * 8 + j) * 32 + bb], uh);
            acc = fmaf(uh, vsh[i * 257 + b], acc);
        }
    }
    int idx = (c * 1152 + n) * 16 + i;
    g_blog[idx] = store ? acc : (g_blog[idx] + acc);
}

__global__ void out_kernel(float* __restrict__ out) {
    int c = blockIdx.x, b = threadIdx.x;
    float s = 0.f;
#pragma unroll
    for (int i = 0; i < 16; i++) {
        float t = g_v[(c * 16 + i) * 256 + b];
        s = fmaf(t, t, s);
    }
    out[b * 10 + c] = s;
}

// ===========================================================================
extern "C" void kernel_launch(void* const* d_in, const int* in_sizes, int n_in,
                              void* d_out, int out_size) {
    const float* x  = (const float*)d_in[0];
    const float* w1 = (const float*)d_in[1];
    const float* b1 = (const float*)d_in[2];
    const float* w2 = (const float*)d_in[3];
    const float* b2 = (const float*)d_in[4];
    const float* W  = (const float*)d_in[5];
    float* out = (float*)d_out;

    const int SMEM_BYTES = 3 * STG;  // 92160
    cudaFuncSetAttribute(conv2_mma_kernel, cudaFuncAttributeMaxDynamicSharedMemorySize,
                         SMEM_BYTES);

    conv1_kernel<<<dim3(256, 16), 128>>>(x, w1, b1);
    prep_kernel<<<593, 256>>>(w2);
    bquant_kernel<<<9216, 256>>>();
    conv2_mma_kernel<<<dim3(2, 144), 256, SMEM_BYTES>>>(b2);  // 4th launch -> profiled
    squashT_kernel<<<1152, 256>>>();

    for (int it = 0; it < 3; it++) {
        if (it > 0) softmax_kernel<<<160, 128>>>();
        sgemm_routing_kernel<<<dim3(32, 10), 128>>>(W, it == 0 ? 1 : 0);
        squashv_kernel<<<160, 256>>>();
        if (it < 2) delta_kernel<<<dim3(144, 10), 128>>>(W, it == 0 ? 1 : 0);
    }
    out_kernel<<<10, 256>>>(out);
}